// round 1
// baseline (speedup 1.0000x reference)
#include <cuda_runtime.h>
#include <math.h>

// Problem dims (fixed by the reference)
constexpr int Bb = 4;
constexpr int Ss = 2048;
constexpr int Dd = 1024;
constexpr int Hh = 16;
constexpr int Hd = 64;
constexpr int MM = Bb * Ss;  // 8192 rows

// Scratch (allocation-free rule: __device__ globals)
__device__ float g_q[MM * Dd];
__device__ float g_k[MM * Dd];
__device__ float g_v[MM * Dd];
__device__ float g_ctx[MM * Dd];

// ---------------------------------------------------------------------------
// SGEMM: C[M,N] = A[M,K] @ W[K,N] + bias[N]
// 128x128 block, BK=8, 256 threads, 8x8 per thread.
// ---------------------------------------------------------------------------
__global__ __launch_bounds__(256) void sgemm_bias(
    const float* __restrict__ A, const float* __restrict__ W,
    const float* __restrict__ bias, float* __restrict__ C,
    int M, int N, int K)
{
    __shared__ __align__(16) float As[8][128];
    __shared__ __align__(16) float Bs[8][128];

    const int tid = threadIdx.x;
    const int tx = tid & 15;
    const int ty = tid >> 4;
    const int bm = blockIdx.y;
    const int bn = blockIdx.x;

    const float* Ab = A + (size_t)bm * 128 * K;
    const float* Wb = W + bn * 128;

    const int a_row = tid >> 1;          // 0..127
    const int a_col = (tid & 1) * 4;     // 0 or 4
    const int b_row = tid >> 5;          // 0..7
    const int b_col = (tid & 31) * 4;    // 0..124

    float acc[8][8];
#pragma unroll
    for (int i = 0; i < 8; i++)
#pragma unroll
        for (int j = 0; j < 8; j++) acc[i][j] = 0.0f;

    for (int kt = 0; kt < K; kt += 8) {
        float4 av = *(const float4*)(Ab + (size_t)a_row * K + kt + a_col);
        float4 bv = *(const float4*)(Wb + (size_t)(kt + b_row) * N + b_col);
        As[a_col + 0][a_row] = av.x;
        As[a_col + 1][a_row] = av.y;
        As[a_col + 2][a_row] = av.z;
        As[a_col + 3][a_row] = av.w;
        *(float4*)&Bs[b_row][b_col] = bv;
        __syncthreads();

#pragma unroll
        for (int k = 0; k < 8; k++) {
            float ar[8], br[8];
            *(float4*)&ar[0] = *(const float4*)&As[k][ty * 8];
            *(float4*)&ar[4] = *(const float4*)&As[k][ty * 8 + 4];
            *(float4*)&br[0] = *(const float4*)&Bs[k][tx * 8];
            *(float4*)&br[4] = *(const float4*)&Bs[k][tx * 8 + 4];
#pragma unroll
            for (int i = 0; i < 8; i++)
#pragma unroll
                for (int j = 0; j < 8; j++)
                    acc[i][j] += ar[i] * br[j];
        }
        __syncthreads();
    }

#pragma unroll
    for (int i = 0; i < 8; i++) {
        const int row = bm * 128 + ty * 8 + i;
        float* Crow = C + (size_t)row * N + bn * 128 + tx * 8;
#pragma unroll
        for (int j = 0; j < 8; j++)
            acc[i][j] += bias[bn * 128 + tx * 8 + j];
        *(float4*)Crow = *(float4*)&acc[i][0];
        *(float4*)(Crow + 4) = *(float4*)&acc[i][4];
    }
}

// ---------------------------------------------------------------------------
// Flash attention (fp32, causal). One CTA = 64 query rows of one (b,h).
// Q/K stored d-major in smem with XOR-4 swizzle -> conflict-free LDS.128 in
// both GEMM phases. P overwrites K's buffer (48KB total static smem).
// ---------------------------------------------------------------------------
__device__ __forceinline__ int swz(int a, int b) {
    // element (a = major dim 0..63, b = minor dim 0..63)
    return a * 64 + ((((b >> 2) ^ (a & 15)) << 2) | (b & 3));
}

__global__ __launch_bounds__(256) void attn_fwd(
    const float* __restrict__ Q, const float* __restrict__ K,
    const float* __restrict__ V, float* __restrict__ Octx)
{
    __shared__ __align__(16) float Qs[4096];  // [d][row] swizzled
    __shared__ __align__(16) float KP[4096];  // K: [d][key] swizzled, then P: [key][row] swizzled
    __shared__ __align__(16) float Vs[4096];  // [key][d] natural

    const int tid = threadIdx.x;
    const int tx = tid & 15;
    const int ty = tid >> 4;
    // schedule longest blocks (largest qt) first
    const int qt = (int)gridDim.x - 1 - (int)blockIdx.x;
    const int b = blockIdx.y >> 4;
    const int h = blockIdx.y & 15;
    const size_t base = ((size_t)b * Ss) * Dd + (size_t)h * Hd;

    const int lr = tid >> 4;            // row within a load pass
    const int ld0 = (tid & 15) * 4;     // d offset (float4)

    // Load Q tile, pre-scaled by 1/sqrt(HD)
#pragma unroll
    for (int it = 0; it < 4; it++) {
        const int r = lr + it * 16;
        float4 qv = *(const float4*)(Q + base + (size_t)(qt * 64 + r) * Dd + ld0);
        Qs[swz(ld0 + 0, r)] = qv.x * 0.125f;
        Qs[swz(ld0 + 1, r)] = qv.y * 0.125f;
        Qs[swz(ld0 + 2, r)] = qv.z * 0.125f;
        Qs[swz(ld0 + 3, r)] = qv.w * 0.125f;
    }

    float O[4][4];
    float m[4], l[4];
#pragma unroll
    for (int i = 0; i < 4; i++) {
        m[i] = -1e30f;
        l[i] = 0.0f;
#pragma unroll
        for (int j = 0; j < 4; j++) O[i][j] = 0.0f;
    }

    for (int kt = 0; kt <= qt; kt++) {
        // Load K (swizzled, d-major) and V (natural) tiles
#pragma unroll
        for (int it = 0; it < 4; it++) {
            const int r = lr + it * 16;
            float4 kv = *(const float4*)(K + base + (size_t)(kt * 64 + r) * Dd + ld0);
            KP[swz(ld0 + 0, r)] = kv.x;
            KP[swz(ld0 + 1, r)] = kv.y;
            KP[swz(ld0 + 2, r)] = kv.z;
            KP[swz(ld0 + 3, r)] = kv.w;
            float4 vv = *(const float4*)(V + base + (size_t)(kt * 64 + r) * Dd + ld0);
            *(float4*)&Vs[r * 64 + ld0] = vv;
        }
        __syncthreads();

        // Scores: S[r][c] = sum_d Qs[d][r] * Ks[d][c]
        float S[4][4];
#pragma unroll
        for (int i = 0; i < 4; i++)
#pragma unroll
            for (int j = 0; j < 4; j++) S[i][j] = 0.0f;

#pragma unroll 8
        for (int d = 0; d < 64; d++) {
            float qa[4], ka[4];
            *(float4*)qa = *(const float4*)&Qs[d * 64 + ((ty ^ (d & 15)) << 2)];
            *(float4*)ka = *(const float4*)&KP[d * 64 + ((tx ^ (d & 15)) << 2)];
#pragma unroll
            for (int i = 0; i < 4; i++)
#pragma unroll
                for (int j = 0; j < 4; j++)
                    S[i][j] += qa[i] * ka[j];
        }

        // Causal mask (diagonal tile only)
        if (kt == qt) {
#pragma unroll
            for (int i = 0; i < 4; i++)
#pragma unroll
                for (int j = 0; j < 4; j++)
                    if (tx * 4 + j > ty * 4 + i) S[i][j] = -3.0e38f;
        }

        __syncthreads();  // K reads done; KP is about to become P

        // Online softmax + write P (transposed, swizzled) into KP
#pragma unroll
        for (int i = 0; i < 4; i++) {
            float mx = fmaxf(fmaxf(S[i][0], S[i][1]), fmaxf(S[i][2], S[i][3]));
            mx = fmaxf(mx, __shfl_xor_sync(0xffffffffu, mx, 1));
            mx = fmaxf(mx, __shfl_xor_sync(0xffffffffu, mx, 2));
            mx = fmaxf(mx, __shfl_xor_sync(0xffffffffu, mx, 4));
            mx = fmaxf(mx, __shfl_xor_sync(0xffffffffu, mx, 8));
            const float mnew = fmaxf(m[i], mx);
            const float alpha = __expf(m[i] - mnew);
            float p0 = __expf(S[i][0] - mnew);
            float p1 = __expf(S[i][1] - mnew);
            float p2 = __expf(S[i][2] - mnew);
            float p3 = __expf(S[i][3] - mnew);
            float rs = p0 + p1 + p2 + p3;
            rs += __shfl_xor_sync(0xffffffffu, rs, 1);
            rs += __shfl_xor_sync(0xffffffffu, rs, 2);
            rs += __shfl_xor_sync(0xffffffffu, rs, 4);
            rs += __shfl_xor_sync(0xffffffffu, rs, 8);
            l[i] = l[i] * alpha + rs;
            m[i] = mnew;
#pragma unroll
            for (int j = 0; j < 4; j++) O[i][j] *= alpha;
            const int r = ty * 4 + i;
            KP[swz(tx * 4 + 0, r)] = p0;
            KP[swz(tx * 4 + 1, r)] = p1;
            KP[swz(tx * 4 + 2, r)] = p2;
            KP[swz(tx * 4 + 3, r)] = p3;
        }
        __syncthreads();

        // O[r][c] += sum_j P[j][r] * V[j][c]
#pragma unroll 8
        for (int j = 0; j < 64; j++) {
            float pa[4], va[4];
            *(float4*)pa = *(const float4*)&KP[j * 64 + ((ty ^ (j & 15)) << 2)];
            *(float4*)va = *(const float4*)&Vs[j * 64 + tx * 4];
#pragma unroll
            for (int i = 0; i < 4; i++)
#pragma unroll
                for (int c = 0; c < 4; c++)
                    O[i][c] += pa[i] * va[c];
        }
        __syncthreads();  // before next tile overwrites KP/Vs
    }

    // Normalize and write context: [B,S,D] with col = h*64 + c
#pragma unroll
    for (int i = 0; i < 4; i++) {
        const float inv = 1.0f / l[i];
        float4 o;
        o.x = O[i][0] * inv;
        o.y = O[i][1] * inv;
        o.z = O[i][2] * inv;
        o.w = O[i][3] * inv;
        *(float4*)(Octx + base + (size_t)(qt * 64 + ty * 4 + i) * Dd + tx * 4) = o;
    }
}

// ---------------------------------------------------------------------------
extern "C" void kernel_launch(void* const* d_in, const int* in_sizes, int n_in,
                              void* d_out, int out_size)
{
    const float* x  = (const float*)d_in[0];
    const float* Wq = (const float*)d_in[1];
    const float* bq = (const float*)d_in[2];
    const float* Wk = (const float*)d_in[3];
    const float* bk = (const float*)d_in[4];
    const float* Wv = (const float*)d_in[5];
    const float* bv = (const float*)d_in[6];
    const float* Wo = (const float*)d_in[7];
    const float* bo = (const float*)d_in[8];
    float* out = (float*)d_out;

    float *q, *k, *v, *ctx;
    cudaGetSymbolAddress((void**)&q, g_q);
    cudaGetSymbolAddress((void**)&k, g_k);
    cudaGetSymbolAddress((void**)&v, g_v);
    cudaGetSymbolAddress((void**)&ctx, g_ctx);

    dim3 gg(Dd / 128, MM / 128);
    sgemm_bias<<<gg, 256>>>(x, Wq, bq, q, MM, Dd, Dd);
    sgemm_bias<<<gg, 256>>>(x, Wk, bk, k, MM, Dd, Dd);
    sgemm_bias<<<gg, 256>>>(x, Wv, bv, v, MM, Dd, Dd);

    attn_fwd<<<dim3(Ss / 64, Bb * Hh), 256>>>(q, k, v, ctx);

    sgemm_bias<<<gg, 256>>>(ctx, Wo, bo, out, MM, Dd, Dd);
}

// round 4
// speedup vs baseline: 1.3952x; 1.3952x over previous
#include <cuda_runtime.h>
#include <cuda_bf16.h>
#include <stdint.h>
#include <math.h>

// Problem dims (fixed by the reference)
constexpr int Bb = 4;
constexpr int Ss = 2048;
constexpr int Dd = 1024;
constexpr int Hh = 16;
constexpr int Hd = 64;
constexpr int MM = Bb * Ss;  // 8192 rows

// Scratch (allocation-free rule: __device__ globals), 256B-aligned.
__device__ __align__(256) float g_q[MM * Dd];
__device__ __align__(256) float g_k[MM * Dd];
__device__ __align__(256) float g_v[MM * Dd];
__device__ __align__(256) float g_ctx[MM * Dd];
__device__ __align__(256) __nv_bfloat16 g_xh[MM * Dd];
__device__ __align__(256) __nv_bfloat16 g_xl[MM * Dd];
__device__ __align__(256) __nv_bfloat16 g_ch[MM * Dd];
__device__ __align__(256) __nv_bfloat16 g_cl[MM * Dd];
__device__ __align__(256) __nv_bfloat16 g_wth[4 * Dd * Dd];
__device__ __align__(256) __nv_bfloat16 g_wtl[4 * Dd * Dd];

// ---------------------------------------------------------------------------
// PTX helpers — ONLY sm_80/sm_90 base-target features (harness ptxas target is
// plain sm_100: no tcgen05 / no '.a' accelerated features!)
// ---------------------------------------------------------------------------
#define CP16(smem, gptr) \
    asm volatile("cp.async.cg.shared.global [%0], [%1], 16;" :: "r"(smem), "l"(gptr))
#define CP_COMMIT() asm volatile("cp.async.commit_group;" ::: "memory")
#define CP_WAIT(n)  asm volatile("cp.async.wait_group %0;" :: "n"(n) : "memory")

#define LDSM4(r, addr) \
    asm volatile("ldmatrix.sync.aligned.m8n8.x4.shared.b16 {%0,%1,%2,%3}, [%4];" \
        : "=r"((r)[0]), "=r"((r)[1]), "=r"((r)[2]), "=r"((r)[3]) : "r"(addr))

#define MMA_BF16(d, a, b) \
    asm volatile("mma.sync.aligned.m16n8k16.row.col.f32.bf16.bf16.f32 " \
        "{%0,%1,%2,%3}, {%4,%5,%6,%7}, {%8,%9}, {%0,%1,%2,%3};" \
        : "+f"((d)[0]), "+f"((d)[1]), "+f"((d)[2]), "+f"((d)[3]) \
        : "r"((a)[0]), "r"((a)[1]), "r"((a)[2]), "r"((a)[3]), \
          "r"((b)[0]), "r"((b)[1]))

// ---------------------------------------------------------------------------
// Split fp32 -> (bf16 hi, bf16 lo residual), elementwise
// ---------------------------------------------------------------------------
__global__ __launch_bounds__(256) void split_hilo_bf16(
    const float* __restrict__ A, __nv_bfloat16* __restrict__ Hi,
    __nv_bfloat16* __restrict__ Lo)
{
    int i = (blockIdx.x * 256 + threadIdx.x) * 4;
    float4 a = *(const float4*)(A + i);
    __nv_bfloat16 hx = __float2bfloat16(a.x);
    __nv_bfloat16 hy = __float2bfloat16(a.y);
    __nv_bfloat16 hz = __float2bfloat16(a.z);
    __nv_bfloat16 hw = __float2bfloat16(a.w);
    __nv_bfloat162 h0; h0.x = hx; h0.y = hy;
    __nv_bfloat162 h1; h1.x = hz; h1.y = hw;
    __nv_bfloat162 l0, l1;
    l0.x = __float2bfloat16(a.x - __bfloat162float(hx));
    l0.y = __float2bfloat16(a.y - __bfloat162float(hy));
    l1.x = __float2bfloat16(a.z - __bfloat162float(hz));
    l1.y = __float2bfloat16(a.w - __bfloat162float(hw));
    *(__nv_bfloat162*)(Hi + i)     = h0;
    *(__nv_bfloat162*)(Hi + i + 2) = h1;
    *(__nv_bfloat162*)(Lo + i)     = l0;
    *(__nv_bfloat162*)(Lo + i + 2) = l1;
}

// ---------------------------------------------------------------------------
// Transpose + split: W[K=1024, N=1024] -> Th[n*K+k], Tl[n*K+k] (bf16)
// ---------------------------------------------------------------------------
__global__ __launch_bounds__(256) void transpose_split_bf16(
    const float* __restrict__ W, __nv_bfloat16* __restrict__ Th,
    __nv_bfloat16* __restrict__ Tl)
{
    __shared__ float t[32][33];
    const int tx = threadIdx.x, ty = threadIdx.y;
    const int n0 = blockIdx.x * 32, k0 = blockIdx.y * 32;
#pragma unroll
    for (int i = 0; i < 32; i += 8)
        t[ty + i][tx] = W[(size_t)(k0 + ty + i) * Dd + n0 + tx];
    __syncthreads();
#pragma unroll
    for (int i = 0; i < 32; i += 8) {
        float a = t[tx][ty + i];          // = W[k0+tx][n0+ty+i]
        __nv_bfloat16 h = __float2bfloat16(a);
        size_t o = (size_t)(n0 + ty + i) * Dd + k0 + tx;
        Th[o] = h;
        Tl[o] = __float2bfloat16(a - __bfloat162float(h));
    }
}

// ---------------------------------------------------------------------------
// bf16x3 mma.sync GEMM: C[M,N] = A[M,K] @ Bt[N,K]^T + bias
// A given as (Ah, Al) bf16, Bt as (Bh, Bl) bf16.
// 128x128 tile / CTA, 8 warps (2x4), warp tile 64x32, BK=16,
// double-buffered cp.async. Row stride 48B -> conflict-free ldmatrix.
// ---------------------------------------------------------------------------
constexpr int NKC = Dd / 16;         // 64 K-chunks
constexpr int ROWB = 48;             // 32B data + 16B pad per row
constexpr int ARR = 128 * ROWB;      // 6144 B per sub-array
constexpr int STG = 4 * ARR;         // 24576 B per stage (Ah, Al, Bh, Bl)
constexpr int GSMEM = 2 * STG;       // 49152 B (fits default 48KB dyn smem)

extern __shared__ char dynsmem[];

__global__ __launch_bounds__(256) void gemm_bf16x3(
    const __nv_bfloat16* __restrict__ Ah, const __nv_bfloat16* __restrict__ Al,
    const __nv_bfloat16* __restrict__ Bh, const __nv_bfloat16* __restrict__ Bl,
    const float* __restrict__ bias, float* __restrict__ C)
{
    const int K = Dd, N = Dd;
    const uint32_t sb = (uint32_t)__cvta_generic_to_shared(dynsmem);
    const int tid = threadIdx.x;
    const int wid = tid >> 5, lane = tid & 31;
    const int bm = blockIdx.y, bn = blockIdx.x;
    const int wm = wid >> 2, wn = wid & 3;   // warp grid 2 (m) x 4 (n)

    // ---- global load mapping: thread t -> row t/2, 16B chunk t&1 ----
    const int lrow = tid >> 1;
    const int lhb = tid & 1;
    const uint32_t woff = (uint32_t)(lrow * ROWB + lhb * 16);
    const __nv_bfloat16* gAh = Ah + (size_t)(bm * 128 + lrow) * K + lhb * 8;
    const __nv_bfloat16* gAl = Al + (size_t)(bm * 128 + lrow) * K + lhb * 8;
    const __nv_bfloat16* gBh = Bh + (size_t)(bn * 128 + lrow) * K + lhb * 8;
    const __nv_bfloat16* gBl = Bl + (size_t)(bn * 128 + lrow) * K + lhb * 8;

    auto load_stage = [&](int s, int c) {
        const uint32_t st = sb + s * STG + woff;
        const size_t go = (size_t)c * 16;
        CP16(st + 0 * ARR, gAh + go);
        CP16(st + 1 * ARR, gAl + go);
        CP16(st + 2 * ARR, gBh + go);
        CP16(st + 3 * ARR, gBl + go);
        CP_COMMIT();
    };

    // ---- ldmatrix per-lane offsets ----
    // A (m16k16 frag, x4): tiles = lanes/8: t0 rows m0..+7 k0-7; t1 rows+8 k0-7;
    //                      t2 rows m0..+7 k8-15; t3 rows+8 k8-15
    const int lt = lane >> 3, ltr = lane & 7;
    const uint32_t aoff =
        (uint32_t)((wm * 64 + ltr + ((lt & 1) << 3)) * ROWB + (lt >> 1) * 16);
    // B (n16k16 from two n8 frags, x4): t0 n0..+7 k0-7; t1 n0..+7 k8-15;
    //                                   t2 n+8 k0-7;   t3 n+8 k8-15
    const uint32_t boff =
        (uint32_t)((wn * 32 + ltr + ((lt >> 1) << 3)) * ROWB + (lt & 1) * 16);

    float acc[4][4][4];
#pragma unroll
    for (int mi = 0; mi < 4; mi++)
#pragma unroll
        for (int ni = 0; ni < 4; ni++)
#pragma unroll
            for (int r = 0; r < 4; r++) acc[mi][ni][r] = 0.0f;

    load_stage(0, 0);
    load_stage(1, 1);

    for (int c = 0; c < NKC; c++) {
        if (c + 2 < NKC) { CP_WAIT(1); } else { CP_WAIT(0); }
        __syncthreads();
        const uint32_t st = sb + (c & 1) * STG;

        uint32_t bhf[2][4], blf[2][4];
#pragma unroll
        for (int nip = 0; nip < 2; nip++) {
            LDSM4(bhf[nip], st + 2 * ARR + boff + nip * (16 * ROWB));
            LDSM4(blf[nip], st + 3 * ARR + boff + nip * (16 * ROWB));
        }
#pragma unroll
        for (int mi = 0; mi < 4; mi++) {
            uint32_t ahf[4], alf[4];
            LDSM4(ahf, st + 0 * ARR + aoff + mi * (16 * ROWB));
            LDSM4(alf, st + 1 * ARR + aoff + mi * (16 * ROWB));
#pragma unroll
            for (int ni = 0; ni < 4; ni++) {
                uint32_t* ph = &bhf[ni >> 1][(ni & 1) * 2];
                uint32_t* pl = &blf[ni >> 1][(ni & 1) * 2];
                MMA_BF16(acc[mi][ni], ahf, ph);
                MMA_BF16(acc[mi][ni], ahf, pl);
                MMA_BF16(acc[mi][ni], alf, ph);
            }
        }
        __syncthreads();
        if (c + 2 < NKC) load_stage(c & 1, c + 2);
    }

    // ---- epilogue: bias + store ----
    const int r0 = bm * 128 + wm * 64 + (lane >> 2);
    const int c0 = bn * 128 + wn * 32 + (lane & 3) * 2;
#pragma unroll
    for (int mi = 0; mi < 4; mi++) {
#pragma unroll
        for (int ni = 0; ni < 4; ni++) {
            const int col = c0 + ni * 8;
            const float bx = bias[col], by = bias[col + 1];
            float2 v0, v1;
            v0.x = acc[mi][ni][0] + bx; v0.y = acc[mi][ni][1] + by;
            v1.x = acc[mi][ni][2] + bx; v1.y = acc[mi][ni][3] + by;
            *(float2*)(C + (size_t)(r0 + mi * 16) * N + col) = v0;
            *(float2*)(C + (size_t)(r0 + mi * 16 + 8) * N + col) = v1;
        }
    }
}

// ---------------------------------------------------------------------------
// Flash attention (fp32, causal) — unchanged from Round 1 (passed)
// ---------------------------------------------------------------------------
__device__ __forceinline__ int swz(int a, int b) {
    return a * 64 + ((((b >> 2) ^ (a & 15)) << 2) | (b & 3));
}

__global__ __launch_bounds__(256) void attn_fwd(
    const float* __restrict__ Q, const float* __restrict__ K,
    const float* __restrict__ V, float* __restrict__ Octx)
{
    __shared__ __align__(16) float Qs[4096];
    __shared__ __align__(16) float KP[4096];
    __shared__ __align__(16) float Vs[4096];

    const int tid = threadIdx.x;
    const int tx = tid & 15;
    const int ty = tid >> 4;
    const int qt = (int)gridDim.x - 1 - (int)blockIdx.x;
    const int b = blockIdx.y >> 4;
    const int h = blockIdx.y & 15;
    const size_t base = ((size_t)b * Ss) * Dd + (size_t)h * Hd;

    const int lr = tid >> 4;
    const int ld0 = (tid & 15) * 4;

#pragma unroll
    for (int it = 0; it < 4; it++) {
        const int r = lr + it * 16;
        float4 qv = *(const float4*)(Q + base + (size_t)(qt * 64 + r) * Dd + ld0);
        Qs[swz(ld0 + 0, r)] = qv.x * 0.125f;
        Qs[swz(ld0 + 1, r)] = qv.y * 0.125f;
        Qs[swz(ld0 + 2, r)] = qv.z * 0.125f;
        Qs[swz(ld0 + 3, r)] = qv.w * 0.125f;
    }

    float O[4][4];
    float m[4], l[4];
#pragma unroll
    for (int i = 0; i < 4; i++) {
        m[i] = -1e30f;
        l[i] = 0.0f;
#pragma unroll
        for (int j = 0; j < 4; j++) O[i][j] = 0.0f;
    }

    for (int kt = 0; kt <= qt; kt++) {
#pragma unroll
        for (int it = 0; it < 4; it++) {
            const int r = lr + it * 16;
            float4 kv = *(const float4*)(K + base + (size_t)(kt * 64 + r) * Dd + ld0);
            KP[swz(ld0 + 0, r)] = kv.x;
            KP[swz(ld0 + 1, r)] = kv.y;
            KP[swz(ld0 + 2, r)] = kv.z;
            KP[swz(ld0 + 3, r)] = kv.w;
            float4 vv = *(const float4*)(V + base + (size_t)(kt * 64 + r) * Dd + ld0);
            *(float4*)&Vs[r * 64 + ld0] = vv;
        }
        __syncthreads();

        float S[4][4];
#pragma unroll
        for (int i = 0; i < 4; i++)
#pragma unroll
            for (int j = 0; j < 4; j++) S[i][j] = 0.0f;

#pragma unroll 8
        for (int d = 0; d < 64; d++) {
            float qa[4], ka[4];
            *(float4*)qa = *(const float4*)&Qs[d * 64 + ((ty ^ (d & 15)) << 2)];
            *(float4*)ka = *(const float4*)&KP[d * 64 + ((tx ^ (d & 15)) << 2)];
#pragma unroll
            for (int i = 0; i < 4; i++)
#pragma unroll
                for (int j = 0; j < 4; j++)
                    S[i][j] += qa[i] * ka[j];
        }

        if (kt == qt) {
#pragma unroll
            for (int i = 0; i < 4; i++)
#pragma unroll
                for (int j = 0; j < 4; j++)
                    if (tx * 4 + j > ty * 4 + i) S[i][j] = -3.0e38f;
        }

        __syncthreads();

#pragma unroll
        for (int i = 0; i < 4; i++) {
            float mx = fmaxf(fmaxf(S[i][0], S[i][1]), fmaxf(S[i][2], S[i][3]));
            mx = fmaxf(mx, __shfl_xor_sync(0xffffffffu, mx, 1));
            mx = fmaxf(mx, __shfl_xor_sync(0xffffffffu, mx, 2));
            mx = fmaxf(mx, __shfl_xor_sync(0xffffffffu, mx, 4));
            mx = fmaxf(mx, __shfl_xor_sync(0xffffffffu, mx, 8));
            const float mnew = fmaxf(m[i], mx);
            const float alpha = __expf(m[i] - mnew);
            float p0 = __expf(S[i][0] - mnew);
            float p1 = __expf(S[i][1] - mnew);
            float p2 = __expf(S[i][2] - mnew);
            float p3 = __expf(S[i][3] - mnew);
            float rs = p0 + p1 + p2 + p3;
            rs += __shfl_xor_sync(0xffffffffu, rs, 1);
            rs += __shfl_xor_sync(0xffffffffu, rs, 2);
            rs += __shfl_xor_sync(0xffffffffu, rs, 4);
            rs += __shfl_xor_sync(0xffffffffu, rs, 8);
            l[i] = l[i] * alpha + rs;
            m[i] = mnew;
#pragma unroll
            for (int j = 0; j < 4; j++) O[i][j] *= alpha;
            const int r = ty * 4 + i;
            KP[swz(tx * 4 + 0, r)] = p0;
            KP[swz(tx * 4 + 1, r)] = p1;
            KP[swz(tx * 4 + 2, r)] = p2;
            KP[swz(tx * 4 + 3, r)] = p3;
        }
        __syncthreads();

#pragma unroll 8
        for (int j = 0; j < 64; j++) {
            float pa[4], va[4];
            *(float4*)pa = *(const float4*)&KP[j * 64 + ((ty ^ (j & 15)) << 2)];
            *(float4*)va = *(const float4*)&Vs[j * 64 + tx * 4];
#pragma unroll
            for (int i = 0; i < 4; i++)
#pragma unroll
                for (int c = 0; c < 4; c++)
                    O[i][c] += pa[i] * va[c];
        }
        __syncthreads();
    }

#pragma unroll
    for (int i = 0; i < 4; i++) {
        const float inv = 1.0f / l[i];
        float4 o;
        o.x = O[i][0] * inv;
        o.y = O[i][1] * inv;
        o.z = O[i][2] * inv;
        o.w = O[i][3] * inv;
        *(float4*)(Octx + base + (size_t)(qt * 64 + ty * 4 + i) * Dd + tx * 4) = o;
    }
}

// ---------------------------------------------------------------------------
extern "C" void kernel_launch(void* const* d_in, const int* in_sizes, int n_in,
                              void* d_out, int out_size)
{
    const float* x  = (const float*)d_in[0];
    const float* Wq = (const float*)d_in[1];
    const float* bq = (const float*)d_in[2];
    const float* Wk = (const float*)d_in[3];
    const float* bk = (const float*)d_in[4];
    const float* Wv = (const float*)d_in[5];
    const float* bv = (const float*)d_in[6];
    const float* Wo = (const float*)d_in[7];
    const float* bo = (const float*)d_in[8];
    float* out = (float*)d_out;

    float *q, *k, *v, *ctx;
    __nv_bfloat16 *xh, *xl, *ch, *cl, *wth, *wtl;
    cudaGetSymbolAddress((void**)&q, g_q);
    cudaGetSymbolAddress((void**)&k, g_k);
    cudaGetSymbolAddress((void**)&v, g_v);
    cudaGetSymbolAddress((void**)&ctx, g_ctx);
    cudaGetSymbolAddress((void**)&xh, g_xh);
    cudaGetSymbolAddress((void**)&xl, g_xl);
    cudaGetSymbolAddress((void**)&ch, g_ch);
    cudaGetSymbolAddress((void**)&cl, g_cl);
    cudaGetSymbolAddress((void**)&wth, g_wth);
    cudaGetSymbolAddress((void**)&wtl, g_wtl);

    const int WSZ = Dd * Dd;
    dim3 tg(32, 32), tb(32, 8);
    transpose_split_bf16<<<tg, tb>>>(Wq, wth + 0 * WSZ, wtl + 0 * WSZ);
    transpose_split_bf16<<<tg, tb>>>(Wk, wth + 1 * WSZ, wtl + 1 * WSZ);
    transpose_split_bf16<<<tg, tb>>>(Wv, wth + 2 * WSZ, wtl + 2 * WSZ);
    transpose_split_bf16<<<tg, tb>>>(Wo, wth + 3 * WSZ, wtl + 3 * WSZ);

    split_hilo_bf16<<<(MM * Dd) / 1024, 256>>>(x, xh, xl);

    dim3 gg(Dd / 128, MM / 128);
    gemm_bf16x3<<<gg, 256, GSMEM>>>(xh, xl, wth + 0 * WSZ, wtl + 0 * WSZ, bq, q);
    gemm_bf16x3<<<gg, 256, GSMEM>>>(xh, xl, wth + 1 * WSZ, wtl + 1 * WSZ, bk, k);
    gemm_bf16x3<<<gg, 256, GSMEM>>>(xh, xl, wth + 2 * WSZ, wtl + 2 * WSZ, bv, v);

    attn_fwd<<<dim3(Ss / 64, Bb * Hh), 256>>>(q, k, v, ctx);

    split_hilo_bf16<<<(MM * Dd) / 1024, 256>>>(ctx, ch, cl);
    gemm_bf16x3<<<gg, 256, GSMEM>>>(ch, cl, wth + 3 * WSZ, wtl + 3 * WSZ, bo, out);
}

// round 6
// speedup vs baseline: 2.7884x; 1.9985x over previous
#include <cuda_runtime.h>
#include <cuda_bf16.h>
#include <stdint.h>
#include <math.h>

// Problem dims (fixed by the reference)
constexpr int Bb = 4;
constexpr int Ss = 2048;
constexpr int Dd = 1024;
constexpr int Hh = 16;
constexpr int Hd = 64;
constexpr int MM = Bb * Ss;  // 8192 rows

// Scratch (allocation-free rule: __device__ globals), 256B-aligned.
__device__ __align__(256) __nv_bfloat16 g_xh[MM * Dd];
__device__ __align__(256) __nv_bfloat16 g_xl[MM * Dd];
__device__ __align__(256) __nv_bfloat16 g_qh[MM * Dd];
__device__ __align__(256) __nv_bfloat16 g_ql[MM * Dd];
__device__ __align__(256) __nv_bfloat16 g_kh[MM * Dd];
__device__ __align__(256) __nv_bfloat16 g_kl[MM * Dd];
__device__ __align__(256) __nv_bfloat16 g_vh[MM * Dd];
__device__ __align__(256) __nv_bfloat16 g_vl[MM * Dd];
__device__ __align__(256) __nv_bfloat16 g_ch[MM * Dd];
__device__ __align__(256) __nv_bfloat16 g_cl[MM * Dd];
__device__ __align__(256) __nv_bfloat16 g_wth[4 * Dd * Dd];
__device__ __align__(256) __nv_bfloat16 g_wtl[4 * Dd * Dd];

// ---------------------------------------------------------------------------
// PTX helpers — ONLY base sm_100-target features (no tcgen05 / '.a' features).
// NO cudaFuncSetAttribute anywhere: raising smem limits trips the harness's
// "device limits changed" guard (R2/R5 container deaths). All kernels stay
// within the default 48KB dynamic smem.
// ---------------------------------------------------------------------------
#define CP16(smem, gptr) \
    asm volatile("cp.async.cg.shared.global [%0], [%1], 16;" :: "r"(smem), "l"(gptr))
#define CP_COMMIT() asm volatile("cp.async.commit_group;" ::: "memory")
#define CP_WAIT(n)  asm volatile("cp.async.wait_group %0;" :: "n"(n) : "memory")

#define LDSM4(r, addr) \
    asm volatile("ldmatrix.sync.aligned.m8n8.x4.shared.b16 {%0,%1,%2,%3}, [%4];" \
        : "=r"((r)[0]), "=r"((r)[1]), "=r"((r)[2]), "=r"((r)[3]) : "r"(addr))

#define LDSMT4(r, addr) \
    asm volatile("ldmatrix.sync.aligned.m8n8.x4.trans.shared.b16 {%0,%1,%2,%3}, [%4];" \
        : "=r"((r)[0]), "=r"((r)[1]), "=r"((r)[2]), "=r"((r)[3]) : "r"(addr))

#define MMA_BF16(d, a, b) \
    asm volatile("mma.sync.aligned.m16n8k16.row.col.f32.bf16.bf16.f32 " \
        "{%0,%1,%2,%3}, {%4,%5,%6,%7}, {%8,%9}, {%0,%1,%2,%3};" \
        : "+f"((d)[0]), "+f"((d)[1]), "+f"((d)[2]), "+f"((d)[3]) \
        : "r"((a)[0]), "r"((a)[1]), "r"((a)[2]), "r"((a)[3]), \
          "r"((b)[0]), "r"((b)[1]))

__device__ __forceinline__ uint32_t packh2(float a, float b) {
    __nv_bfloat162 t;
    t.x = __float2bfloat16(a);
    t.y = __float2bfloat16(b);
    return *(uint32_t*)&t;
}
__device__ __forceinline__ uint32_t packl2(float a, float b) {
    __nv_bfloat162 t;
    t.x = __float2bfloat16(a - __bfloat162float(__float2bfloat16(a)));
    t.y = __float2bfloat16(b - __bfloat162float(__float2bfloat16(b)));
    return *(uint32_t*)&t;
}

// ---------------------------------------------------------------------------
// Split fp32 -> (bf16 hi, bf16 lo residual), elementwise
// ---------------------------------------------------------------------------
__global__ __launch_bounds__(256) void split_hilo_bf16(
    const float* __restrict__ A, __nv_bfloat16* __restrict__ Hi,
    __nv_bfloat16* __restrict__ Lo)
{
    int i = (blockIdx.x * 256 + threadIdx.x) * 4;
    float4 a = *(const float4*)(A + i);
    *(uint32_t*)(Hi + i)     = packh2(a.x, a.y);
    *(uint32_t*)(Hi + i + 2) = packh2(a.z, a.w);
    *(uint32_t*)(Lo + i)     = packl2(a.x, a.y);
    *(uint32_t*)(Lo + i + 2) = packl2(a.z, a.w);
}

// ---------------------------------------------------------------------------
// Transpose + split: W[K=1024, N=1024] -> Th[n*K+k], Tl[n*K+k] (bf16)
// ---------------------------------------------------------------------------
__global__ __launch_bounds__(256) void transpose_split_bf16(
    const float* __restrict__ W, __nv_bfloat16* __restrict__ Th,
    __nv_bfloat16* __restrict__ Tl)
{
    __shared__ float t[32][33];
    const int tx = threadIdx.x, ty = threadIdx.y;
    const int n0 = blockIdx.x * 32, k0 = blockIdx.y * 32;
#pragma unroll
    for (int i = 0; i < 32; i += 8)
        t[ty + i][tx] = W[(size_t)(k0 + ty + i) * Dd + n0 + tx];
    __syncthreads();
#pragma unroll
    for (int i = 0; i < 32; i += 8) {
        float a = t[tx][ty + i];          // = W[k0+tx][n0+ty+i]
        __nv_bfloat16 h = __float2bfloat16(a);
        size_t o = (size_t)(n0 + ty + i) * Dd + k0 + tx;
        Th[o] = h;
        Tl[o] = __float2bfloat16(a - __bfloat162float(h));
    }
}

// ---------------------------------------------------------------------------
// bf16x3 mma.sync GEMM: C = A[M,K] @ Bt[N,K]^T + bias
// outmode 0: write fp32 C.  outmode 1: write split bf16 (Ch, Cl).
// 128x128 tile / CTA, 8 warps (2x4), warp tile 64x32, BK=16,
// double-buffered cp.async. Row stride 48B -> conflict-free ldmatrix.
// Smem = 49152B = default 48KB limit (NO attribute calls).
// ---------------------------------------------------------------------------
constexpr int NKC = Dd / 16;         // 64 K-chunks
constexpr int ROWB = 48;             // 32B data + 16B pad per row
constexpr int ARR = 128 * ROWB;      // 6144 B per sub-array
constexpr int STG = 4 * ARR;         // 24576 B per stage (Ah, Al, Bh, Bl)
constexpr int GSMEM = 2 * STG;       // 49152 B

extern __shared__ char dynsmem[];

__global__ __launch_bounds__(256) void gemm_bf16x3(
    const __nv_bfloat16* __restrict__ Ah, const __nv_bfloat16* __restrict__ Al,
    const __nv_bfloat16* __restrict__ Bh, const __nv_bfloat16* __restrict__ Bl,
    const float* __restrict__ bias, float* __restrict__ C,
    __nv_bfloat16* __restrict__ Ch, __nv_bfloat16* __restrict__ Cl,
    int outmode)
{
    const int K = Dd, N = Dd;
    const uint32_t sb = (uint32_t)__cvta_generic_to_shared(dynsmem);
    const int tid = threadIdx.x;
    const int wid = tid >> 5, lane = tid & 31;
    const int bm = blockIdx.y, bn = blockIdx.x;
    const int wm = wid >> 2, wn = wid & 3;   // warp grid 2 (m) x 4 (n)

    const int lrow = tid >> 1;
    const int lhb = tid & 1;
    const uint32_t woff = (uint32_t)(lrow * ROWB + lhb * 16);
    const __nv_bfloat16* gAh = Ah + (size_t)(bm * 128 + lrow) * K + lhb * 8;
    const __nv_bfloat16* gAl = Al + (size_t)(bm * 128 + lrow) * K + lhb * 8;
    const __nv_bfloat16* gBh = Bh + (size_t)(bn * 128 + lrow) * K + lhb * 8;
    const __nv_bfloat16* gBl = Bl + (size_t)(bn * 128 + lrow) * K + lhb * 8;

    auto load_stage = [&](int s, int c) {
        const uint32_t st = sb + s * STG + woff;
        const size_t go = (size_t)c * 16;
        CP16(st + 0 * ARR, gAh + go);
        CP16(st + 1 * ARR, gAl + go);
        CP16(st + 2 * ARR, gBh + go);
        CP16(st + 3 * ARR, gBl + go);
        CP_COMMIT();
    };

    const int lt = lane >> 3, ltr = lane & 7;
    const uint32_t aoff =
        (uint32_t)((wm * 64 + ltr + ((lt & 1) << 3)) * ROWB + (lt >> 1) * 16);
    const uint32_t boff =
        (uint32_t)((wn * 32 + ltr + ((lt >> 1) << 3)) * ROWB + (lt & 1) * 16);

    float acc[4][4][4];
#pragma unroll
    for (int mi = 0; mi < 4; mi++)
#pragma unroll
        for (int ni = 0; ni < 4; ni++)
#pragma unroll
            for (int r = 0; r < 4; r++) acc[mi][ni][r] = 0.0f;

    load_stage(0, 0);
    load_stage(1, 1);

    for (int c = 0; c < NKC; c++) {
        if (c + 2 < NKC) { CP_WAIT(1); } else { CP_WAIT(0); }
        __syncthreads();
        const uint32_t st = sb + (c & 1) * STG;

        uint32_t bhf[2][4], blf[2][4];
#pragma unroll
        for (int nip = 0; nip < 2; nip++) {
            LDSM4(bhf[nip], st + 2 * ARR + boff + nip * (16 * ROWB));
            LDSM4(blf[nip], st + 3 * ARR + boff + nip * (16 * ROWB));
        }
#pragma unroll
        for (int mi = 0; mi < 4; mi++) {
            uint32_t ahf[4], alf[4];
            LDSM4(ahf, st + 0 * ARR + aoff + mi * (16 * ROWB));
            LDSM4(alf, st + 1 * ARR + aoff + mi * (16 * ROWB));
#pragma unroll
            for (int ni = 0; ni < 4; ni++) {
                uint32_t* ph = &bhf[ni >> 1][(ni & 1) * 2];
                uint32_t* pl = &blf[ni >> 1][(ni & 1) * 2];
                MMA_BF16(acc[mi][ni], ahf, ph);
                MMA_BF16(acc[mi][ni], ahf, pl);
                MMA_BF16(acc[mi][ni], alf, ph);
            }
        }
        __syncthreads();
        if (c + 2 < NKC) load_stage(c & 1, c + 2);
    }

    // ---- epilogue: bias + store (fp32 or split bf16) ----
    const int r0 = bm * 128 + wm * 64 + (lane >> 2);
    const int c0 = bn * 128 + wn * 32 + (lane & 3) * 2;
#pragma unroll
    for (int mi = 0; mi < 4; mi++) {
#pragma unroll
        for (int ni = 0; ni < 4; ni++) {
            const int col = c0 + ni * 8;
            const float bx = bias[col], by = bias[col + 1];
            const float v0 = acc[mi][ni][0] + bx, v1 = acc[mi][ni][1] + by;
            const float v2 = acc[mi][ni][2] + bx, v3 = acc[mi][ni][3] + by;
            const size_t o0 = (size_t)(r0 + mi * 16) * N + col;
            const size_t o1 = (size_t)(r0 + mi * 16 + 8) * N + col;
            if (outmode == 0) {
                float2 a0; a0.x = v0; a0.y = v1;
                float2 a1; a1.x = v2; a1.y = v3;
                *(float2*)(C + o0) = a0;
                *(float2*)(C + o1) = a1;
            } else {
                *(uint32_t*)(Ch + o0) = packh2(v0, v1);
                *(uint32_t*)(Cl + o0) = packl2(v0, v1);
                *(uint32_t*)(Ch + o1) = packh2(v2, v3);
                *(uint32_t*)(Cl + o1) = packl2(v2, v3);
            }
        }
    }
}

// ---------------------------------------------------------------------------
// Flash attention, bf16x3 mma.sync, causal.
// CTA = 128 q rows of one (b,h); 8 warps x 16 rows. K-tile = 32 keys,
// double-buffered cp.async of (Kh, Kl, Vh, Vl): 2 x 18432B = 36864B < 48KB.
// Q hi/lo staged through the same smem BEFORE the loop. Rows padded to 144B
// -> conflict-free ldmatrix. P split hi/lo in-register; ctx out bf16 hi/lo.
// ---------------------------------------------------------------------------
constexpr int AQT = 128;
constexpr int AKT = 32;
constexpr int AROW = 144;             // 64 bf16 = 128B + 16B pad
constexpr int KARR = AKT * AROW;      // 4608
constexpr int ASTG = 4 * KARR;        // 18432 per stage
constexpr int ASMEM = 2 * ASTG;       // 36864 (< default 48KB; NO attribute)

__global__ __launch_bounds__(256, 1) void attn_bf16(
    const __nv_bfloat16* __restrict__ Qh, const __nv_bfloat16* __restrict__ Ql,
    const __nv_bfloat16* __restrict__ Kh, const __nv_bfloat16* __restrict__ Kl,
    const __nv_bfloat16* __restrict__ Vh, const __nv_bfloat16* __restrict__ Vl,
    __nv_bfloat16* __restrict__ Ch, __nv_bfloat16* __restrict__ Cl)
{
    const uint32_t sb = (uint32_t)__cvta_generic_to_shared(dynsmem);
    const int tid = threadIdx.x;
    const int w = tid >> 5, lane = tid & 31;
    const int qt = (int)gridDim.x - 1 - (int)blockIdx.x;  // longest first
    const int b = blockIdx.y >> 4, h = blockIdx.y & 15;
    const size_t base = ((size_t)b * Ss) * Dd + (size_t)h * Hd;
    const int nkt = 4 * (qt + 1);
    const int lt = lane >> 3, ltr = lane & 7;

    // ---- Stage Q hi/lo through smem [0, 36864), extract A-frags to regs ----
    {
#pragma unroll
        for (int i = 0; i < 4; i++) {
            const int ch = tid + i * 256;             // 0..1023
            const int row = ch >> 3, c16 = ch & 7;    // 128 rows x 8 chunks
            const uint32_t so = (uint32_t)(row * AROW + c16 * 16);
            const size_t go = base + (size_t)(qt * AQT + row) * Dd + c16 * 8;
            CP16(sb + so,         Qh + go);
            CP16(sb + 18432 + so, Ql + go);
        }
        CP_COMMIT();
        CP_WAIT(0);
        __syncthreads();
    }
    uint32_t qhf[4][4], qlf[4][4];
    {
        const uint32_t ao =
            (uint32_t)((w * 16 + ltr + ((lt & 1) << 3)) * AROW + (lt >> 1) * 16);
#pragma unroll
        for (int ks = 0; ks < 4; ks++) {
            LDSM4(qhf[ks], sb + ao + ks * 32);
            LDSM4(qlf[ks], sb + 18432 + ao + ks * 32);
        }
    }
    __syncthreads();

    // ---- K/V tile loader: 4 arrays x 256 16B-chunks, 1 chunk/thread/array --
    auto load_kv = [&](int c, int s) {
        const uint32_t st = sb + s * ASTG;
        const int row = tid >> 3, c16 = tid & 7;      // 32 rows x 8 chunks
        const uint32_t so = (uint32_t)(row * AROW + c16 * 16);
        const size_t go = base + (size_t)(c * AKT + row) * Dd + c16 * 8;
        CP16(st + 0 * KARR + so, Kh + go);
        CP16(st + 1 * KARR + so, Kl + go);
        CP16(st + 2 * KARR + so, Vh + go);
        CP16(st + 3 * KARR + so, Vl + go);
        CP_COMMIT();
    };

    // ldmatrix lane offsets for K (non-trans, [key][d]) and V (trans)
    const uint32_t kbo = (uint32_t)((ltr + ((lt >> 1) << 3)) * AROW + (lt & 1) * 16);
    const uint32_t vbo = (uint32_t)((ltr + ((lt & 1) << 3)) * AROW + (lt >> 1) * 16);

    float oacc[8][4];
#pragma unroll
    for (int nb = 0; nb < 8; nb++)
#pragma unroll
        for (int r = 0; r < 4; r++) oacc[nb][r] = 0.0f;
    float sm0 = -1e30f, sm1 = -1e30f, sl0 = 0.0f, sl1 = 0.0f;

    load_kv(0, 0);

    for (int c = 0; c < nkt; c++) {
        if (c + 1 < nkt) { load_kv(c + 1, (c + 1) & 1); CP_WAIT(1); }
        else CP_WAIT(0);
        __syncthreads();
        const uint32_t st = sb + (c & 1) * ASTG;

        // ---- S = Q K^T (3-term bf16): 128 q x 32 keys ----
        float sacc[4][4];
#pragma unroll
        for (int nb = 0; nb < 4; nb++)
#pragma unroll
            for (int r = 0; r < 4; r++) sacc[nb][r] = 0.0f;

#pragma unroll
        for (int ks = 0; ks < 4; ks++) {
#pragma unroll
            for (int ng = 0; ng < 2; ng++) {
                uint32_t kh4[4], kl4[4];
                const uint32_t a = st + kbo + ng * (16 * AROW) + ks * 32;
                LDSM4(kh4, a);
                LDSM4(kl4, a + KARR);
                MMA_BF16(sacc[2 * ng],     qhf[ks], kh4);
                MMA_BF16(sacc[2 * ng],     qhf[ks], kl4);
                MMA_BF16(sacc[2 * ng],     qlf[ks], kh4);
                MMA_BF16(sacc[2 * ng + 1], qhf[ks], kh4 + 2);
                MMA_BF16(sacc[2 * ng + 1], qhf[ks], kl4 + 2);
                MMA_BF16(sacc[2 * ng + 1], qlf[ks], kh4 + 2);
            }
        }

        // ---- online softmax (rows r0 = lane/4, r1 = r0+8 in warp tile) ----
        const bool diag = (c >= 4 * qt);
        const int row0 = qt * AQT + w * 16 + (lane >> 2);
        float mx0 = -1e30f, mx1 = -1e30f;
#pragma unroll
        for (int nb = 0; nb < 4; nb++) {
            float s0 = sacc[nb][0] * 0.125f, s1 = sacc[nb][1] * 0.125f;
            float s2 = sacc[nb][2] * 0.125f, s3 = sacc[nb][3] * 0.125f;
            if (diag) {
                const int col = c * AKT + nb * 8 + (lane & 3) * 2;
                if (col     > row0)     s0 = -1e30f;
                if (col + 1 > row0)     s1 = -1e30f;
                if (col     > row0 + 8) s2 = -1e30f;
                if (col + 1 > row0 + 8) s3 = -1e30f;
            }
            sacc[nb][0] = s0; sacc[nb][1] = s1; sacc[nb][2] = s2; sacc[nb][3] = s3;
            mx0 = fmaxf(mx0, fmaxf(s0, s1));
            mx1 = fmaxf(mx1, fmaxf(s2, s3));
        }
        mx0 = fmaxf(mx0, __shfl_xor_sync(0xffffffffu, mx0, 1));
        mx0 = fmaxf(mx0, __shfl_xor_sync(0xffffffffu, mx0, 2));
        mx1 = fmaxf(mx1, __shfl_xor_sync(0xffffffffu, mx1, 1));
        mx1 = fmaxf(mx1, __shfl_xor_sync(0xffffffffu, mx1, 2));
        const float mn0 = fmaxf(sm0, mx0), mn1 = fmaxf(sm1, mx1);
        const float al0 = __expf(sm0 - mn0), al1 = __expf(sm1 - mn1);
        float rs0 = 0.0f, rs1 = 0.0f;
#pragma unroll
        for (int nb = 0; nb < 4; nb++) {
            sacc[nb][0] = __expf(sacc[nb][0] - mn0);
            sacc[nb][1] = __expf(sacc[nb][1] - mn0);
            sacc[nb][2] = __expf(sacc[nb][2] - mn1);
            sacc[nb][3] = __expf(sacc[nb][3] - mn1);
            rs0 += sacc[nb][0] + sacc[nb][1];
            rs1 += sacc[nb][2] + sacc[nb][3];
        }
        rs0 += __shfl_xor_sync(0xffffffffu, rs0, 1);
        rs0 += __shfl_xor_sync(0xffffffffu, rs0, 2);
        rs1 += __shfl_xor_sync(0xffffffffu, rs1, 1);
        rs1 += __shfl_xor_sync(0xffffffffu, rs1, 2);
        sl0 = sl0 * al0 + rs0;
        sl1 = sl1 * al1 + rs1;
        sm0 = mn0; sm1 = mn1;
#pragma unroll
        for (int nb = 0; nb < 8; nb++) {
            oacc[nb][0] *= al0; oacc[nb][1] *= al0;
            oacc[nb][2] *= al1; oacc[nb][3] *= al1;
        }

        // ---- O += P V (3-term bf16; V^T frags via ldmatrix.trans) ----
#pragma unroll
        for (int ks = 0; ks < 2; ks++) {
            uint32_t phf4[4], plf4[4];
            phf4[0] = packh2(sacc[2 * ks][0], sacc[2 * ks][1]);
            phf4[1] = packh2(sacc[2 * ks][2], sacc[2 * ks][3]);
            phf4[2] = packh2(sacc[2 * ks + 1][0], sacc[2 * ks + 1][1]);
            phf4[3] = packh2(sacc[2 * ks + 1][2], sacc[2 * ks + 1][3]);
            plf4[0] = packl2(sacc[2 * ks][0], sacc[2 * ks][1]);
            plf4[1] = packl2(sacc[2 * ks][2], sacc[2 * ks][3]);
            plf4[2] = packl2(sacc[2 * ks + 1][0], sacc[2 * ks + 1][1]);
            plf4[3] = packl2(sacc[2 * ks + 1][2], sacc[2 * ks + 1][3]);
#pragma unroll
            for (int dg = 0; dg < 4; dg++) {
                uint32_t vh4[4], vl4[4];
                const uint32_t a = st + 2 * KARR + vbo + ks * (16 * AROW) + dg * 32;
                LDSMT4(vh4, a);
                LDSMT4(vl4, a + KARR);
                MMA_BF16(oacc[2 * dg],     phf4, vh4);
                MMA_BF16(oacc[2 * dg],     phf4, vl4);
                MMA_BF16(oacc[2 * dg],     plf4, vh4);
                MMA_BF16(oacc[2 * dg + 1], phf4, vh4 + 2);
                MMA_BF16(oacc[2 * dg + 1], phf4, vl4 + 2);
                MMA_BF16(oacc[2 * dg + 1], plf4, vh4 + 2);
            }
        }
        __syncthreads();
    }

    // ---- normalize + write ctx as bf16 hi/lo ----
    const float inv0 = 1.0f / sl0, inv1 = 1.0f / sl1;
    const size_t tr0 = (size_t)(b * Ss + qt * AQT + w * 16 + (lane >> 2));
    const int dcol = h * Hd + (lane & 3) * 2;
#pragma unroll
    for (int nb = 0; nb < 8; nb++) {
        const float o0 = oacc[nb][0] * inv0, o1 = oacc[nb][1] * inv0;
        const float o2 = oacc[nb][2] * inv1, o3 = oacc[nb][3] * inv1;
        const size_t g0 = tr0 * Dd + dcol + nb * 8;
        const size_t g1 = (tr0 + 8) * Dd + dcol + nb * 8;
        *(uint32_t*)(Ch + g0) = packh2(o0, o1);
        *(uint32_t*)(Cl + g0) = packl2(o0, o1);
        *(uint32_t*)(Ch + g1) = packh2(o2, o3);
        *(uint32_t*)(Cl + g1) = packl2(o2, o3);
    }
}

// ---------------------------------------------------------------------------
extern "C" void kernel_launch(void* const* d_in, const int* in_sizes, int n_in,
                              void* d_out, int out_size)
{
    const float* x  = (const float*)d_in[0];
    const float* Wq = (const float*)d_in[1];
    const float* bq = (const float*)d_in[2];
    const float* Wk = (const float*)d_in[3];
    const float* bk = (const float*)d_in[4];
    const float* Wv = (const float*)d_in[5];
    const float* bv = (const float*)d_in[6];
    const float* Wo = (const float*)d_in[7];
    const float* bo = (const float*)d_in[8];
    float* out = (float*)d_out;

    __nv_bfloat16 *xh, *xl, *qh, *ql, *kh, *kl, *vh, *vl, *ch, *cl, *wth, *wtl;
    cudaGetSymbolAddress((void**)&xh, g_xh);
    cudaGetSymbolAddress((void**)&xl, g_xl);
    cudaGetSymbolAddress((void**)&qh, g_qh);
    cudaGetSymbolAddress((void**)&ql, g_ql);
    cudaGetSymbolAddress((void**)&kh, g_kh);
    cudaGetSymbolAddress((void**)&kl, g_kl);
    cudaGetSymbolAddress((void**)&vh, g_vh);
    cudaGetSymbolAddress((void**)&vl, g_vl);
    cudaGetSymbolAddress((void**)&ch, g_ch);
    cudaGetSymbolAddress((void**)&cl, g_cl);
    cudaGetSymbolAddress((void**)&wth, g_wth);
    cudaGetSymbolAddress((void**)&wtl, g_wtl);

    const int WSZ = Dd * Dd;
    dim3 tg(32, 32), tb(32, 8);
    transpose_split_bf16<<<tg, tb>>>(Wq, wth + 0 * WSZ, wtl + 0 * WSZ);
    transpose_split_bf16<<<tg, tb>>>(Wk, wth + 1 * WSZ, wtl + 1 * WSZ);
    transpose_split_bf16<<<tg, tb>>>(Wv, wth + 2 * WSZ, wtl + 2 * WSZ);
    transpose_split_bf16<<<tg, tb>>>(Wo, wth + 3 * WSZ, wtl + 3 * WSZ);

    split_hilo_bf16<<<(MM * Dd) / 1024, 256>>>(x, xh, xl);

    dim3 gg(Dd / 128, MM / 128);
    gemm_bf16x3<<<gg, 256, GSMEM>>>(xh, xl, wth + 0 * WSZ, wtl + 0 * WSZ, bq,
                                    nullptr, qh, ql, 1);
    gemm_bf16x3<<<gg, 256, GSMEM>>>(xh, xl, wth + 1 * WSZ, wtl + 1 * WSZ, bk,
                                    nullptr, kh, kl, 1);
    gemm_bf16x3<<<gg, 256, GSMEM>>>(xh, xl, wth + 2 * WSZ, wtl + 2 * WSZ, bv,
                                    nullptr, vh, vl, 1);

    attn_bf16<<<dim3(Ss / AQT, Bb * Hh), 256, ASMEM>>>(qh, ql, kh, kl, vh, vl, ch, cl);

    gemm_bf16x3<<<gg, 256, GSMEM>>>(ch, cl, wth + 3 * WSZ, wtl + 3 * WSZ, bo,
                                    out, nullptr, nullptr, 0);
}

// round 7
// speedup vs baseline: 2.9970x; 1.0748x over previous
#include <cuda_runtime.h>
#include <cuda_bf16.h>
#include <stdint.h>
#include <math.h>

// Problem dims (fixed by the reference)
constexpr int Bb = 4;
constexpr int Ss = 2048;
constexpr int Dd = 1024;
constexpr int Hh = 16;
constexpr int Hd = 64;
constexpr int MM = Bb * Ss;  // 8192 rows

// Scratch (allocation-free rule: __device__ globals), 256B-aligned.
__device__ __align__(256) __nv_bfloat16 g_xh[MM * Dd];
__device__ __align__(256) __nv_bfloat16 g_xl[MM * Dd];
__device__ __align__(256) __nv_bfloat16 g_qh[MM * Dd];
__device__ __align__(256) __nv_bfloat16 g_ql[MM * Dd];
__device__ __align__(256) __nv_bfloat16 g_kh[MM * Dd];
__device__ __align__(256) __nv_bfloat16 g_kl[MM * Dd];
__device__ __align__(256) __nv_bfloat16 g_vh[MM * Dd];
__device__ __align__(256) __nv_bfloat16 g_vl[MM * Dd];
__device__ __align__(256) __nv_bfloat16 g_ch[MM * Dd];
__device__ __align__(256) __nv_bfloat16 g_cl[MM * Dd];
__device__ __align__(256) __nv_bfloat16 g_wth[4 * Dd * Dd];
__device__ __align__(256) __nv_bfloat16 g_wtl[4 * Dd * Dd];

// ---------------------------------------------------------------------------
// PTX helpers — ONLY base sm_100-target features (no tcgen05 / '.a').
// NO cudaFuncSetAttribute anywhere (harness "device limits changed" guard).
// ---------------------------------------------------------------------------
#define CP16(smem, gptr) \
    asm volatile("cp.async.cg.shared.global [%0], [%1], 16;" :: "r"(smem), "l"(gptr))
#define CP_COMMIT() asm volatile("cp.async.commit_group;" ::: "memory")
#define CP_WAIT(n)  asm volatile("cp.async.wait_group %0;" :: "n"(n) : "memory")

#define LDSM4(r, addr) \
    asm volatile("ldmatrix.sync.aligned.m8n8.x4.shared.b16 {%0,%1,%2,%3}, [%4];" \
        : "=r"((r)[0]), "=r"((r)[1]), "=r"((r)[2]), "=r"((r)[3]) : "r"(addr))

#define LDSMT4(r, addr) \
    asm volatile("ldmatrix.sync.aligned.m8n8.x4.trans.shared.b16 {%0,%1,%2,%3}, [%4];" \
        : "=r"((r)[0]), "=r"((r)[1]), "=r"((r)[2]), "=r"((r)[3]) : "r"(addr))

#define MMA_BF16(d, a, b) \
    asm volatile("mma.sync.aligned.m16n8k16.row.col.f32.bf16.bf16.f32 " \
        "{%0,%1,%2,%3}, {%4,%5,%6,%7}, {%8,%9}, {%0,%1,%2,%3};" \
        : "+f"((d)[0]), "+f"((d)[1]), "+f"((d)[2]), "+f"((d)[3]) \
        : "r"((a)[0]), "r"((a)[1]), "r"((a)[2]), "r"((a)[3]), \
          "r"((b)[0]), "r"((b)[1]))

__device__ __forceinline__ uint32_t packh2(float a, float b) {
    __nv_bfloat162 t;
    t.x = __float2bfloat16(a);
    t.y = __float2bfloat16(b);
    return *(uint32_t*)&t;
}
__device__ __forceinline__ uint32_t packl2(float a, float b) {
    __nv_bfloat162 t;
    t.x = __float2bfloat16(a - __bfloat162float(__float2bfloat16(a)));
    t.y = __float2bfloat16(b - __bfloat162float(__float2bfloat16(b)));
    return *(uint32_t*)&t;
}

// ---------------------------------------------------------------------------
// Split fp32 -> (bf16 hi, bf16 lo residual), elementwise
// ---------------------------------------------------------------------------
__global__ __launch_bounds__(256) void split_hilo_bf16(
    const float* __restrict__ A, __nv_bfloat16* __restrict__ Hi,
    __nv_bfloat16* __restrict__ Lo)
{
    int i = (blockIdx.x * 256 + threadIdx.x) * 4;
    float4 a = *(const float4*)(A + i);
    *(uint32_t*)(Hi + i)     = packh2(a.x, a.y);
    *(uint32_t*)(Hi + i + 2) = packh2(a.z, a.w);
    *(uint32_t*)(Lo + i)     = packl2(a.x, a.y);
    *(uint32_t*)(Lo + i + 2) = packl2(a.z, a.w);
}

// ---------------------------------------------------------------------------
// Transpose + split all 4 weights in ONE launch (blockIdx.z selects W):
// W[K=1024, N=1024] -> Th[z*WSZ + n*K + k], Tl[...]
// ---------------------------------------------------------------------------
__global__ __launch_bounds__(256) void transpose_split4_bf16(
    const float* __restrict__ W0, const float* __restrict__ W1,
    const float* __restrict__ W2, const float* __restrict__ W3,
    __nv_bfloat16* __restrict__ Th, __nv_bfloat16* __restrict__ Tl)
{
    __shared__ float t[32][33];
    const int z = blockIdx.z;
    const float* W = z == 0 ? W0 : (z == 1 ? W1 : (z == 2 ? W2 : W3));
    const size_t zo = (size_t)z * Dd * Dd;
    const int tx = threadIdx.x, ty = threadIdx.y;
    const int n0 = blockIdx.x * 32, k0 = blockIdx.y * 32;
#pragma unroll
    for (int i = 0; i < 32; i += 8)
        t[ty + i][tx] = W[(size_t)(k0 + ty + i) * Dd + n0 + tx];
    __syncthreads();
#pragma unroll
    for (int i = 0; i < 32; i += 8) {
        float a = t[tx][ty + i];          // = W[k0+tx][n0+ty+i]
        __nv_bfloat16 h = __float2bfloat16(a);
        size_t o = zo + (size_t)(n0 + ty + i) * Dd + k0 + tx;
        Th[o] = h;
        Tl[o] = __float2bfloat16(a - __bfloat162float(h));
    }
}

// ---------------------------------------------------------------------------
// bf16x3 mma.sync GEMM.
//   nsplit==3 (QKV merged): grid.x = 24. sel = bn>>3 picks (bias, out) among
//     3 outputs; B rows taken from contiguous Wt base at bn*128.
//   nsplit==1 (output proj): grid.x = 8, fp32 C output.
// 128x128 tile / CTA, 8 warps (2x4), warp tile 64x32, BK=16,
// double-buffered cp.async (distance 2). Row stride 48B -> conflict-free
// ldmatrix. Smem = 49152B = default 48KB. __launch_bounds__(256,2) pins
// regs <= 128 so occupancy 2 is guaranteed.
// ---------------------------------------------------------------------------
constexpr int NKC = Dd / 16;         // 64 K-chunks
constexpr int ROWB = 48;             // 32B data + 16B pad per row
constexpr int ARR = 128 * ROWB;      // 6144 B per sub-array
constexpr int STG = 4 * ARR;         // 24576 B per stage (Ah, Al, Bh, Bl)
constexpr int GSMEM = 2 * STG;       // 49152 B

extern __shared__ char dynsmem[];

__global__ __launch_bounds__(256, 2) void gemm_bf16x3(
    const __nv_bfloat16* __restrict__ Ah, const __nv_bfloat16* __restrict__ Al,
    const __nv_bfloat16* __restrict__ Bt_h, const __nv_bfloat16* __restrict__ Bt_l,
    const float* __restrict__ b0, const float* __restrict__ b1,
    const float* __restrict__ b2,
    __nv_bfloat16* __restrict__ o0h, __nv_bfloat16* __restrict__ o0l,
    __nv_bfloat16* __restrict__ o1h, __nv_bfloat16* __restrict__ o1l,
    __nv_bfloat16* __restrict__ o2h, __nv_bfloat16* __restrict__ o2l,
    float* __restrict__ C)
{
    const int K = Dd, N = Dd;
    const uint32_t sb = (uint32_t)__cvta_generic_to_shared(dynsmem);
    const int tid = threadIdx.x;
    const int wid = tid >> 5, lane = tid & 31;
    const int bm = blockIdx.y, bn = blockIdx.x;
    const int sel = bn >> 3, bnl = bn & 7;
    const int wm = wid >> 2, wn = wid & 3;   // warp grid 2 (m) x 4 (n)

    const float* bias = sel == 0 ? b0 : (sel == 1 ? b1 : b2);
    __nv_bfloat16* Ch = sel == 0 ? o0h : (sel == 1 ? o1h : o2h);
    __nv_bfloat16* Cl = sel == 0 ? o0l : (sel == 1 ? o1l : o2l);

    const int lrow = tid >> 1;
    const int lhb = tid & 1;
    const uint32_t woff = (uint32_t)(lrow * ROWB + lhb * 16);
    const __nv_bfloat16* gAh = Ah + (size_t)(bm * 128 + lrow) * K + lhb * 8;
    const __nv_bfloat16* gAl = Al + (size_t)(bm * 128 + lrow) * K + lhb * 8;
    const __nv_bfloat16* gBh = Bt_h + (size_t)(bn * 128 + lrow) * K + lhb * 8;
    const __nv_bfloat16* gBl = Bt_l + (size_t)(bn * 128 + lrow) * K + lhb * 8;

    auto load_stage = [&](int s, int c) {
        const uint32_t st = sb + s * STG + woff;
        const size_t go = (size_t)c * 16;
        CP16(st + 0 * ARR, gAh + go);
        CP16(st + 1 * ARR, gAl + go);
        CP16(st + 2 * ARR, gBh + go);
        CP16(st + 3 * ARR, gBl + go);
        CP_COMMIT();
    };

    const int lt = lane >> 3, ltr = lane & 7;
    const uint32_t aoff =
        (uint32_t)((wm * 64 + ltr + ((lt & 1) << 3)) * ROWB + (lt >> 1) * 16);
    const uint32_t boff =
        (uint32_t)((wn * 32 + ltr + ((lt >> 1) << 3)) * ROWB + (lt & 1) * 16);

    float acc[4][4][4];
#pragma unroll
    for (int mi = 0; mi < 4; mi++)
#pragma unroll
        for (int ni = 0; ni < 4; ni++)
#pragma unroll
            for (int r = 0; r < 4; r++) acc[mi][ni][r] = 0.0f;

    load_stage(0, 0);
    load_stage(1, 1);

    for (int c = 0; c < NKC; c++) {
        if (c + 2 < NKC) { CP_WAIT(1); } else { CP_WAIT(0); }
        __syncthreads();
        const uint32_t st = sb + (c & 1) * STG;

        uint32_t bhf[2][4], blf[2][4];
#pragma unroll
        for (int nip = 0; nip < 2; nip++) {
            LDSM4(bhf[nip], st + 2 * ARR + boff + nip * (16 * ROWB));
            LDSM4(blf[nip], st + 3 * ARR + boff + nip * (16 * ROWB));
        }
#pragma unroll
        for (int mi = 0; mi < 4; mi++) {
            uint32_t ahf[4], alf[4];
            LDSM4(ahf, st + 0 * ARR + aoff + mi * (16 * ROWB));
            LDSM4(alf, st + 1 * ARR + aoff + mi * (16 * ROWB));
#pragma unroll
            for (int ni = 0; ni < 4; ni++) {
                uint32_t* ph = &bhf[ni >> 1][(ni & 1) * 2];
                uint32_t* pl = &blf[ni >> 1][(ni & 1) * 2];
                MMA_BF16(acc[mi][ni], ahf, ph);
                MMA_BF16(acc[mi][ni], ahf, pl);
                MMA_BF16(acc[mi][ni], alf, ph);
            }
        }
        __syncthreads();
        if (c + 2 < NKC) load_stage(c & 1, c + 2);
    }

    // ---- epilogue: bias + store (fp32 C or split bf16) ----
    const int r0 = bm * 128 + wm * 64 + (lane >> 2);
    const int c0 = bnl * 128 + wn * 32 + (lane & 3) * 2;
#pragma unroll
    for (int mi = 0; mi < 4; mi++) {
#pragma unroll
        for (int ni = 0; ni < 4; ni++) {
            const int col = c0 + ni * 8;
            const float bx = bias[col], by = bias[col + 1];
            const float v0 = acc[mi][ni][0] + bx, v1 = acc[mi][ni][1] + by;
            const float v2 = acc[mi][ni][2] + bx, v3 = acc[mi][ni][3] + by;
            const size_t o0 = (size_t)(r0 + mi * 16) * N + col;
            const size_t o1 = (size_t)(r0 + mi * 16 + 8) * N + col;
            if (C) {
                float2 a0; a0.x = v0; a0.y = v1;
                float2 a1; a1.x = v2; a1.y = v3;
                *(float2*)(C + o0) = a0;
                *(float2*)(C + o1) = a1;
            } else {
                *(uint32_t*)(Ch + o0) = packh2(v0, v1);
                *(uint32_t*)(Cl + o0) = packl2(v0, v1);
                *(uint32_t*)(Ch + o1) = packh2(v2, v3);
                *(uint32_t*)(Cl + o1) = packl2(v2, v3);
            }
        }
    }
}

// ---------------------------------------------------------------------------
// Flash attention, bf16x3 mma.sync, causal. (Same as R6 except
// __launch_bounds__(256,2) to pin occupancy.)
// ---------------------------------------------------------------------------
constexpr int AQT = 128;
constexpr int AKT = 32;
constexpr int AROW = 144;             // 64 bf16 = 128B + 16B pad
constexpr int KARR = AKT * AROW;      // 4608
constexpr int ASTG = 4 * KARR;        // 18432 per stage
constexpr int ASMEM = 2 * ASTG;       // 36864 (< default 48KB)

__global__ __launch_bounds__(256, 2) void attn_bf16(
    const __nv_bfloat16* __restrict__ Qh, const __nv_bfloat16* __restrict__ Ql,
    const __nv_bfloat16* __restrict__ Kh, const __nv_bfloat16* __restrict__ Kl,
    const __nv_bfloat16* __restrict__ Vh, const __nv_bfloat16* __restrict__ Vl,
    __nv_bfloat16* __restrict__ Ch, __nv_bfloat16* __restrict__ Cl)
{
    const uint32_t sb = (uint32_t)__cvta_generic_to_shared(dynsmem);
    const int tid = threadIdx.x;
    const int w = tid >> 5, lane = tid & 31;
    const int qt = (int)gridDim.x - 1 - (int)blockIdx.x;  // longest first
    const int b = blockIdx.y >> 4, h = blockIdx.y & 15;
    const size_t base = ((size_t)b * Ss) * Dd + (size_t)h * Hd;
    const int nkt = 4 * (qt + 1);
    const int lt = lane >> 3, ltr = lane & 7;

    // ---- Stage Q hi/lo through smem, extract A-frags to regs ----
    {
#pragma unroll
        for (int i = 0; i < 4; i++) {
            const int ch = tid + i * 256;             // 0..1023
            const int row = ch >> 3, c16 = ch & 7;    // 128 rows x 8 chunks
            const uint32_t so = (uint32_t)(row * AROW + c16 * 16);
            const size_t go = base + (size_t)(qt * AQT + row) * Dd + c16 * 8;
            CP16(sb + so,         Qh + go);
            CP16(sb + 18432 + so, Ql + go);
        }
        CP_COMMIT();
        CP_WAIT(0);
        __syncthreads();
    }
    uint32_t qhf[4][4], qlf[4][4];
    {
        const uint32_t ao =
            (uint32_t)((w * 16 + ltr + ((lt & 1) << 3)) * AROW + (lt >> 1) * 16);
#pragma unroll
        for (int ks = 0; ks < 4; ks++) {
            LDSM4(qhf[ks], sb + ao + ks * 32);
            LDSM4(qlf[ks], sb + 18432 + ao + ks * 32);
        }
    }
    __syncthreads();

    // ---- K/V tile loader: 4 arrays x 256 16B-chunks, 1 chunk/thread/array --
    auto load_kv = [&](int c, int s) {
        const uint32_t st = sb + s * ASTG;
        const int row = tid >> 3, c16 = tid & 7;      // 32 rows x 8 chunks
        const uint32_t so = (uint32_t)(row * AROW + c16 * 16);
        const size_t go = base + (size_t)(c * AKT + row) * Dd + c16 * 8;
        CP16(st + 0 * KARR + so, Kh + go);
        CP16(st + 1 * KARR + so, Kl + go);
        CP16(st + 2 * KARR + so, Vh + go);
        CP16(st + 3 * KARR + so, Vl + go);
        CP_COMMIT();
    };

    // ldmatrix lane offsets for K (non-trans, [key][d]) and V (trans)
    const uint32_t kbo = (uint32_t)((ltr + ((lt >> 1) << 3)) * AROW + (lt & 1) * 16);
    const uint32_t vbo = (uint32_t)((ltr + ((lt & 1) << 3)) * AROW + (lt >> 1) * 16);

    float oacc[8][4];
#pragma unroll
    for (int nb = 0; nb < 8; nb++)
#pragma unroll
        for (int r = 0; r < 4; r++) oacc[nb][r] = 0.0f;
    float sm0 = -1e30f, sm1 = -1e30f, sl0 = 0.0f, sl1 = 0.0f;

    load_kv(0, 0);

    for (int c = 0; c < nkt; c++) {
        if (c + 1 < nkt) { load_kv(c + 1, (c + 1) & 1); CP_WAIT(1); }
        else CP_WAIT(0);
        __syncthreads();
        const uint32_t st = sb + (c & 1) * ASTG;

        // ---- S = Q K^T (3-term bf16): 128 q x 32 keys ----
        float sacc[4][4];
#pragma unroll
        for (int nb = 0; nb < 4; nb++)
#pragma unroll
            for (int r = 0; r < 4; r++) sacc[nb][r] = 0.0f;

#pragma unroll
        for (int ks = 0; ks < 4; ks++) {
#pragma unroll
            for (int ng = 0; ng < 2; ng++) {
                uint32_t kh4[4], kl4[4];
                const uint32_t a = st + kbo + ng * (16 * AROW) + ks * 32;
                LDSM4(kh4, a);
                LDSM4(kl4, a + KARR);
                MMA_BF16(sacc[2 * ng],     qhf[ks], kh4);
                MMA_BF16(sacc[2 * ng],     qhf[ks], kl4);
                MMA_BF16(sacc[2 * ng],     qlf[ks], kh4);
                MMA_BF16(sacc[2 * ng + 1], qhf[ks], kh4 + 2);
                MMA_BF16(sacc[2 * ng + 1], qhf[ks], kl4 + 2);
                MMA_BF16(sacc[2 * ng + 1], qlf[ks], kh4 + 2);
            }
        }

        // ---- online softmax ----
        const bool diag = (c >= 4 * qt);
        const int row0 = qt * AQT + w * 16 + (lane >> 2);
        float mx0 = -1e30f, mx1 = -1e30f;
#pragma unroll
        for (int nb = 0; nb < 4; nb++) {
            float s0 = sacc[nb][0] * 0.125f, s1 = sacc[nb][1] * 0.125f;
            float s2 = sacc[nb][2] * 0.125f, s3 = sacc[nb][3] * 0.125f;
            if (diag) {
                const int col = c * AKT + nb * 8 + (lane & 3) * 2;
                if (col     > row0)     s0 = -1e30f;
                if (col + 1 > row0)     s1 = -1e30f;
                if (col     > row0 + 8) s2 = -1e30f;
                if (col + 1 > row0 + 8) s3 = -1e30f;
            }
            sacc[nb][0] = s0; sacc[nb][1] = s1; sacc[nb][2] = s2; sacc[nb][3] = s3;
            mx0 = fmaxf(mx0, fmaxf(s0, s1));
            mx1 = fmaxf(mx1, fmaxf(s2, s3));
        }
        mx0 = fmaxf(mx0, __shfl_xor_sync(0xffffffffu, mx0, 1));
        mx0 = fmaxf(mx0, __shfl_xor_sync(0xffffffffu, mx0, 2));
        mx1 = fmaxf(mx1, __shfl_xor_sync(0xffffffffu, mx1, 1));
        mx1 = fmaxf(mx1, __shfl_xor_sync(0xffffffffu, mx1, 2));
        const float mn0 = fmaxf(sm0, mx0), mn1 = fmaxf(sm1, mx1);
        const float al0 = __expf(sm0 - mn0), al1 = __expf(sm1 - mn1);
        float rs0 = 0.0f, rs1 = 0.0f;
#pragma unroll
        for (int nb = 0; nb < 4; nb++) {
            sacc[nb][0] = __expf(sacc[nb][0] - mn0);
            sacc[nb][1] = __expf(sacc[nb][1] - mn0);
            sacc[nb][2] = __expf(sacc[nb][2] - mn1);
            sacc[nb][3] = __expf(sacc[nb][3] - mn1);
            rs0 += sacc[nb][0] + sacc[nb][1];
            rs1 += sacc[nb][2] + sacc[nb][3];
        }
        rs0 += __shfl_xor_sync(0xffffffffu, rs0, 1);
        rs0 += __shfl_xor_sync(0xffffffffu, rs0, 2);
        rs1 += __shfl_xor_sync(0xffffffffu, rs1, 1);
        rs1 += __shfl_xor_sync(0xffffffffu, rs1, 2);
        sl0 = sl0 * al0 + rs0;
        sl1 = sl1 * al1 + rs1;
        sm0 = mn0; sm1 = mn1;
#pragma unroll
        for (int nb = 0; nb < 8; nb++) {
            oacc[nb][0] *= al0; oacc[nb][1] *= al0;
            oacc[nb][2] *= al1; oacc[nb][3] *= al1;
        }

        // ---- O += P V (3-term bf16; V^T frags via ldmatrix.trans) ----
#pragma unroll
        for (int ks = 0; ks < 2; ks++) {
            uint32_t phf4[4], plf4[4];
            phf4[0] = packh2(sacc[2 * ks][0], sacc[2 * ks][1]);
            phf4[1] = packh2(sacc[2 * ks][2], sacc[2 * ks][3]);
            phf4[2] = packh2(sacc[2 * ks + 1][0], sacc[2 * ks + 1][1]);
            phf4[3] = packh2(sacc[2 * ks + 1][2], sacc[2 * ks + 1][3]);
            plf4[0] = packl2(sacc[2 * ks][0], sacc[2 * ks][1]);
            plf4[1] = packl2(sacc[2 * ks][2], sacc[2 * ks][3]);
            plf4[2] = packl2(sacc[2 * ks + 1][0], sacc[2 * ks + 1][1]);
            plf4[3] = packl2(sacc[2 * ks + 1][2], sacc[2 * ks + 1][3]);
#pragma unroll
            for (int dg = 0; dg < 4; dg++) {
                uint32_t vh4[4], vl4[4];
                const uint32_t a = st + 2 * KARR + vbo + ks * (16 * AROW) + dg * 32;
                LDSMT4(vh4, a);
                LDSMT4(vl4, a + KARR);
                MMA_BF16(oacc[2 * dg],     phf4, vh4);
                MMA_BF16(oacc[2 * dg],     phf4, vl4);
                MMA_BF16(oacc[2 * dg],     plf4, vh4);
                MMA_BF16(oacc[2 * dg + 1], phf4, vh4 + 2);
                MMA_BF16(oacc[2 * dg + 1], phf4, vl4 + 2);
                MMA_BF16(oacc[2 * dg + 1], plf4, vh4 + 2);
            }
        }
        __syncthreads();
    }

    // ---- normalize + write ctx as bf16 hi/lo ----
    const float inv0 = 1.0f / sl0, inv1 = 1.0f / sl1;
    const size_t tr0 = (size_t)(b * Ss + qt * AQT + w * 16 + (lane >> 2));
    const int dcol = h * Hd + (lane & 3) * 2;
#pragma unroll
    for (int nb = 0; nb < 8; nb++) {
        const float o0 = oacc[nb][0] * inv0, o1 = oacc[nb][1] * inv0;
        const float o2 = oacc[nb][2] * inv1, o3 = oacc[nb][3] * inv1;
        const size_t g0 = tr0 * Dd + dcol + nb * 8;
        const size_t g1 = (tr0 + 8) * Dd + dcol + nb * 8;
        *(uint32_t*)(Ch + g0) = packh2(o0, o1);
        *(uint32_t*)(Cl + g0) = packl2(o0, o1);
        *(uint32_t*)(Ch + g1) = packh2(o2, o3);
        *(uint32_t*)(Cl + g1) = packl2(o2, o3);
    }
}

// ---------------------------------------------------------------------------
extern "C" void kernel_launch(void* const* d_in, const int* in_sizes, int n_in,
                              void* d_out, int out_size)
{
    const float* x  = (const float*)d_in[0];
    const float* Wq = (const float*)d_in[1];
    const float* bq = (const float*)d_in[2];
    const float* Wk = (const float*)d_in[3];
    const float* bk = (const float*)d_in[4];
    const float* Wv = (const float*)d_in[5];
    const float* bv = (const float*)d_in[6];
    const float* Wo = (const float*)d_in[7];
    const float* bo = (const float*)d_in[8];
    float* out = (float*)d_out;

    __nv_bfloat16 *xh, *xl, *qh, *ql, *kh, *kl, *vh, *vl, *ch, *cl, *wth, *wtl;
    cudaGetSymbolAddress((void**)&xh, g_xh);
    cudaGetSymbolAddress((void**)&xl, g_xl);
    cudaGetSymbolAddress((void**)&qh, g_qh);
    cudaGetSymbolAddress((void**)&ql, g_ql);
    cudaGetSymbolAddress((void**)&kh, g_kh);
    cudaGetSymbolAddress((void**)&kl, g_kl);
    cudaGetSymbolAddress((void**)&vh, g_vh);
    cudaGetSymbolAddress((void**)&vl, g_vl);
    cudaGetSymbolAddress((void**)&ch, g_ch);
    cudaGetSymbolAddress((void**)&cl, g_cl);
    cudaGetSymbolAddress((void**)&wth, g_wth);
    cudaGetSymbolAddress((void**)&wtl, g_wtl);

    const int WSZ = Dd * Dd;

    // All 4 weight transposes in one launch
    transpose_split4_bf16<<<dim3(32, 32, 4), dim3(32, 8)>>>(Wq, Wk, Wv, Wo, wth, wtl);

    split_hilo_bf16<<<(MM * Dd) / 1024, 256>>>(x, xh, xl);

    // Merged QKV projection: grid.x = 24 covers Wq|Wk|Wv (contiguous in wth)
    gemm_bf16x3<<<dim3(24, MM / 128), 256, GSMEM>>>(
        xh, xl, wth, wtl, bq, bk, bv,
        qh, ql, kh, kl, vh, vl, nullptr);

    attn_bf16<<<dim3(Ss / AQT, Bb * Hh), 256, ASMEM>>>(qh, ql, kh, kl, vh, vl, ch, cl);

    // Output projection: fp32 result
    gemm_bf16x3<<<dim3(8, MM / 128), 256, GSMEM>>>(
        ch, cl, wth + 3 * (size_t)WSZ, wtl + 3 * (size_t)WSZ, bo, bo, bo,
        nullptr, nullptr, nullptr, nullptr, nullptr, nullptr, out);
}

// round 8
// speedup vs baseline: 3.3408x; 1.1147x over previous
#include <cuda_runtime.h>
#include <cuda_bf16.h>
#include <stdint.h>
#include <math.h>

// Problem dims (fixed by the reference)
constexpr int Bb = 4;
constexpr int Ss = 2048;
constexpr int Dd = 1024;
constexpr int Hh = 16;
constexpr int Hd = 64;
constexpr int MM = Bb * Ss;  // 8192 rows

// Scratch (allocation-free rule: __device__ globals), 256B-aligned.
__device__ __align__(256) __nv_bfloat16 g_xh[MM * Dd];
__device__ __align__(256) __nv_bfloat16 g_xl[MM * Dd];
__device__ __align__(256) __nv_bfloat16 g_qh[MM * Dd];
__device__ __align__(256) __nv_bfloat16 g_ql[MM * Dd];
__device__ __align__(256) __nv_bfloat16 g_kh[MM * Dd];
__device__ __align__(256) __nv_bfloat16 g_kl[MM * Dd];
__device__ __align__(256) __nv_bfloat16 g_vh[MM * Dd];
__device__ __align__(256) __nv_bfloat16 g_vl[MM * Dd];
__device__ __align__(256) __nv_bfloat16 g_ch[MM * Dd];
__device__ __align__(256) __nv_bfloat16 g_cl[MM * Dd];
__device__ __align__(256) __nv_bfloat16 g_wth[4 * Dd * Dd];
__device__ __align__(256) __nv_bfloat16 g_wtl[4 * Dd * Dd];

// ---------------------------------------------------------------------------
// PTX helpers — ONLY base sm_100-target features (no tcgen05 / '.a').
// NO cudaFuncSetAttribute anywhere (harness "device limits changed" guard).
// ---------------------------------------------------------------------------
#define CP16(smem, gptr) \
    asm volatile("cp.async.cg.shared.global [%0], [%1], 16;" :: "r"(smem), "l"(gptr))
#define CP_COMMIT() asm volatile("cp.async.commit_group;" ::: "memory")
#define CP_WAIT(n)  asm volatile("cp.async.wait_group %0;" :: "n"(n) : "memory")

#define LDSM4(r, addr) \
    asm volatile("ldmatrix.sync.aligned.m8n8.x4.shared.b16 {%0,%1,%2,%3}, [%4];" \
        : "=r"((r)[0]), "=r"((r)[1]), "=r"((r)[2]), "=r"((r)[3]) : "r"(addr))

#define LDSMT4(r, addr) \
    asm volatile("ldmatrix.sync.aligned.m8n8.x4.trans.shared.b16 {%0,%1,%2,%3}, [%4];" \
        : "=r"((r)[0]), "=r"((r)[1]), "=r"((r)[2]), "=r"((r)[3]) : "r"(addr))

#define MMA_BF16(d, a, b) \
    asm volatile("mma.sync.aligned.m16n8k16.row.col.f32.bf16.bf16.f32 " \
        "{%0,%1,%2,%3}, {%4,%5,%6,%7}, {%8,%9}, {%0,%1,%2,%3};" \
        : "+f"((d)[0]), "+f"((d)[1]), "+f"((d)[2]), "+f"((d)[3]) \
        : "r"((a)[0]), "r"((a)[1]), "r"((a)[2]), "r"((a)[3]), \
          "r"((b)[0]), "r"((b)[1]))

__device__ __forceinline__ uint32_t packh2(float a, float b) {
    __nv_bfloat162 t;
    t.x = __float2bfloat16(a);
    t.y = __float2bfloat16(b);
    return *(uint32_t*)&t;
}
__device__ __forceinline__ uint32_t packl2(float a, float b) {
    __nv_bfloat162 t;
    t.x = __float2bfloat16(a - __bfloat162float(__float2bfloat16(a)));
    t.y = __float2bfloat16(b - __bfloat162float(__float2bfloat16(b)));
    return *(uint32_t*)&t;
}

// ---------------------------------------------------------------------------
// Split fp32 -> (bf16 hi, bf16 lo residual), elementwise
// ---------------------------------------------------------------------------
__global__ __launch_bounds__(256) void split_hilo_bf16(
    const float* __restrict__ A, __nv_bfloat16* __restrict__ Hi,
    __nv_bfloat16* __restrict__ Lo)
{
    int i = (blockIdx.x * 256 + threadIdx.x) * 4;
    float4 a = *(const float4*)(A + i);
    *(uint32_t*)(Hi + i)     = packh2(a.x, a.y);
    *(uint32_t*)(Hi + i + 2) = packh2(a.z, a.w);
    *(uint32_t*)(Lo + i)     = packl2(a.x, a.y);
    *(uint32_t*)(Lo + i + 2) = packl2(a.z, a.w);
}

// ---------------------------------------------------------------------------
// Transpose + split all 4 weights in ONE launch (blockIdx.z selects W)
// ---------------------------------------------------------------------------
__global__ __launch_bounds__(256) void transpose_split4_bf16(
    const float* __restrict__ W0, const float* __restrict__ W1,
    const float* __restrict__ W2, const float* __restrict__ W3,
    __nv_bfloat16* __restrict__ Th, __nv_bfloat16* __restrict__ Tl)
{
    __shared__ float t[32][33];
    const int z = blockIdx.z;
    const float* W = z == 0 ? W0 : (z == 1 ? W1 : (z == 2 ? W2 : W3));
    const size_t zo = (size_t)z * Dd * Dd;
    const int tx = threadIdx.x, ty = threadIdx.y;
    const int n0 = blockIdx.x * 32, k0 = blockIdx.y * 32;
#pragma unroll
    for (int i = 0; i < 32; i += 8)
        t[ty + i][tx] = W[(size_t)(k0 + ty + i) * Dd + n0 + tx];
    __syncthreads();
#pragma unroll
    for (int i = 0; i < 32; i += 8) {
        float a = t[tx][ty + i];
        __nv_bfloat16 h = __float2bfloat16(a);
        size_t o = zo + (size_t)(n0 + ty + i) * Dd + k0 + tx;
        Th[o] = h;
        Tl[o] = __float2bfloat16(a - __bfloat162float(h));
    }
}

// ---------------------------------------------------------------------------
// bf16x3 mma.sync GEMM, 3-stage single-sync pipeline.
// Rows are 32B exact with XOR swizzle (chunk ^ ((row>>2)&1)) -> conflict-free
// ldmatrix, stage = 16384B, 3 stages = 49152B = default smem limit.
// QKV merged (grid.x=24, sel=bn>>3) or fp32 out (C != nullptr).
// Q output (sel==0, bf16 mode) is pre-scaled by 0.125 (exact).
// ---------------------------------------------------------------------------
constexpr int NKC = Dd / 16;         // 64 K-chunks
constexpr int ARR3 = 128 * 32;       // 4096 B per sub-array
constexpr int STG3 = 4 * ARR3;       // 16384 B per stage
constexpr int GSMEM = 3 * STG3;      // 49152 B

extern __shared__ char dynsmem[];

__global__ __launch_bounds__(256, 2) void gemm_bf16x3(
    const __nv_bfloat16* __restrict__ Ah, const __nv_bfloat16* __restrict__ Al,
    const __nv_bfloat16* __restrict__ Bt_h, const __nv_bfloat16* __restrict__ Bt_l,
    const float* __restrict__ b0, const float* __restrict__ b1,
    const float* __restrict__ b2,
    __nv_bfloat16* __restrict__ o0h, __nv_bfloat16* __restrict__ o0l,
    __nv_bfloat16* __restrict__ o1h, __nv_bfloat16* __restrict__ o1l,
    __nv_bfloat16* __restrict__ o2h, __nv_bfloat16* __restrict__ o2l,
    float* __restrict__ C)
{
    const int K = Dd, N = Dd;
    const uint32_t sb = (uint32_t)__cvta_generic_to_shared(dynsmem);
    const int tid = threadIdx.x;
    const int wid = tid >> 5, lane = tid & 31;
    const int bm = blockIdx.y, bn = blockIdx.x;
    const int sel = bn >> 3, bnl = bn & 7;
    const int wm = wid >> 2, wn = wid & 3;

    const float* bias = sel == 0 ? b0 : (sel == 1 ? b1 : b2);
    __nv_bfloat16* Ch = sel == 0 ? o0h : (sel == 1 ? o1h : o2h);
    __nv_bfloat16* Cl = sel == 0 ? o0l : (sel == 1 ? o1l : o2l);
    const float osc = (C == nullptr && sel == 0) ? 0.125f : 1.0f;

    const int lrow = tid >> 1;
    const int lhb = tid & 1;
    const uint32_t woff =
        (uint32_t)(lrow * 32 + ((lhb ^ ((lrow >> 2) & 1)) << 4));
    const __nv_bfloat16* gAh = Ah + (size_t)(bm * 128 + lrow) * K + lhb * 8;
    const __nv_bfloat16* gAl = Al + (size_t)(bm * 128 + lrow) * K + lhb * 8;
    const __nv_bfloat16* gBh = Bt_h + (size_t)(bn * 128 + lrow) * K + lhb * 8;
    const __nv_bfloat16* gBl = Bt_l + (size_t)(bn * 128 + lrow) * K + lhb * 8;

    auto load_stage = [&](int s, int c) {
        const uint32_t st = sb + s * STG3 + woff;
        const size_t go = (size_t)c * 16;
        CP16(st + 0 * ARR3, gAh + go);
        CP16(st + 1 * ARR3, gAl + go);
        CP16(st + 2 * ARR3, gBh + go);
        CP16(st + 3 * ARR3, gBl + go);
        CP_COMMIT();
    };

    const int lt = lane >> 3, ltr = lane & 7;
    const uint32_t aoff =
        (uint32_t)((wm * 64 + ltr + ((lt & 1) << 3)) * 32) +
        ((((lt >> 1) ^ ((ltr >> 2) & 1))) << 4);
    const uint32_t boff =
        (uint32_t)((wn * 32 + ltr + ((lt >> 1) << 3)) * 32) +
        ((((lt & 1) ^ ((ltr >> 2) & 1))) << 4);

    float acc[4][4][4];
#pragma unroll
    for (int mi = 0; mi < 4; mi++)
#pragma unroll
        for (int ni = 0; ni < 4; ni++)
#pragma unroll
            for (int r = 0; r < 4; r++) acc[mi][ni][r] = 0.0f;

    load_stage(0, 0);
    load_stage(1, 1);

    int s = 0;
    for (int c = 0; c < NKC; c++) {
        if (c == NKC - 1) { CP_WAIT(0); } else { CP_WAIT(1); }
        __syncthreads();
        if (c + 2 < NKC) {
            int sn = s + 2; if (sn >= 3) sn -= 3;
            load_stage(sn, c + 2);
        }
        const uint32_t st = sb + s * STG3;

        uint32_t bhf[2][4], blf[2][4];
#pragma unroll
        for (int nip = 0; nip < 2; nip++) {
            LDSM4(bhf[nip], st + 2 * ARR3 + boff + nip * 512);
            LDSM4(blf[nip], st + 3 * ARR3 + boff + nip * 512);
        }
#pragma unroll
        for (int mi = 0; mi < 4; mi++) {
            uint32_t ahf[4], alf[4];
            LDSM4(ahf, st + aoff + mi * 512);
            LDSM4(alf, st + ARR3 + aoff + mi * 512);
#pragma unroll
            for (int ni = 0; ni < 4; ni++) {
                uint32_t* ph = &bhf[ni >> 1][(ni & 1) * 2];
                uint32_t* pl = &blf[ni >> 1][(ni & 1) * 2];
                MMA_BF16(acc[mi][ni], ahf, ph);
                MMA_BF16(acc[mi][ni], ahf, pl);
                MMA_BF16(acc[mi][ni], alf, ph);
            }
        }
        if (++s == 3) s = 0;
    }

    // ---- epilogue: bias (+Q prescale) + store ----
    const int r0 = bm * 128 + wm * 64 + (lane >> 2);
    const int c0 = bnl * 128 + wn * 32 + (lane & 3) * 2;
#pragma unroll
    for (int mi = 0; mi < 4; mi++) {
#pragma unroll
        for (int ni = 0; ni < 4; ni++) {
            const int col = c0 + ni * 8;
            const float bx = bias[col], by = bias[col + 1];
            const float v0 = (acc[mi][ni][0] + bx) * osc;
            const float v1 = (acc[mi][ni][1] + by) * osc;
            const float v2 = (acc[mi][ni][2] + bx) * osc;
            const float v3 = (acc[mi][ni][3] + by) * osc;
            const size_t o0 = (size_t)(r0 + mi * 16) * N + col;
            const size_t o1 = (size_t)(r0 + mi * 16 + 8) * N + col;
            if (C) {
                float2 a0; a0.x = v0; a0.y = v1;
                float2 a1; a1.x = v2; a1.y = v3;
                *(float2*)(C + o0) = a0;
                *(float2*)(C + o1) = a1;
            } else {
                *(uint32_t*)(Ch + o0) = packh2(v0, v1);
                *(uint32_t*)(Cl + o0) = packl2(v0, v1);
                *(uint32_t*)(Ch + o1) = packh2(v2, v3);
                *(uint32_t*)(Cl + o1) = packl2(v2, v3);
            }
        }
    }
}

// ---------------------------------------------------------------------------
// Flash attention, bf16x3 mma.sync, causal. 3-stage single-sync pipeline,
// XOR-swizzled 128B rows (chunk ^ (row&7)): stage = 16384B, 3 stages = 48KB.
// Q pre-scaled by 0.125 upstream. Row-sum reduction deferred to the end.
// ---------------------------------------------------------------------------
constexpr int AQT = 128;
constexpr int AKT = 32;
constexpr int KARR = AKT * 128;       // 4096
constexpr int ASTG = 4 * KARR;        // 16384 per stage (Kh, Kl, Vh, Vl)
constexpr int ASMEM = 3 * ASTG;       // 49152 = default smem limit

__global__ __launch_bounds__(256, 2) void attn_bf16(
    const __nv_bfloat16* __restrict__ Qh, const __nv_bfloat16* __restrict__ Ql,
    const __nv_bfloat16* __restrict__ Kh, const __nv_bfloat16* __restrict__ Kl,
    const __nv_bfloat16* __restrict__ Vh, const __nv_bfloat16* __restrict__ Vl,
    __nv_bfloat16* __restrict__ Ch, __nv_bfloat16* __restrict__ Cl)
{
    const uint32_t sb = (uint32_t)__cvta_generic_to_shared(dynsmem);
    const int tid = threadIdx.x;
    const int w = tid >> 5, lane = tid & 31;
    const int qt = (int)gridDim.x - 1 - (int)blockIdx.x;  // longest first
    const int b = blockIdx.y >> 4, h = blockIdx.y & 15;
    const size_t base = ((size_t)b * Ss) * Dd + (size_t)h * Hd;
    const int nkt = 4 * (qt + 1);
    const int lt = lane >> 3, ltr = lane & 7;

    // ---- Stage Q hi/lo through smem (stages 0-1 region), extract frags ----
    {
#pragma unroll
        for (int i = 0; i < 4; i++) {
            const int ch = tid + i * 256;             // 0..1023
            const int row = ch >> 3, cc = ch & 7;     // 128 rows x 8 chunks
            const uint32_t so =
                (uint32_t)(row * 128 + ((cc ^ (row & 7)) << 4));
            const size_t go = base + (size_t)(qt * AQT + row) * Dd + cc * 8;
            CP16(sb + so,         Qh + go);
            CP16(sb + 16384 + so, Ql + go);
        }
        CP_COMMIT();
        CP_WAIT(0);
        __syncthreads();
    }
    uint32_t qhf[4][4], qlf[4][4];
    {
        const int qr = w * 16 + ltr + ((lt & 1) << 3);
        const uint32_t qrow = (uint32_t)(qr * 128);
#pragma unroll
        for (int ks = 0; ks < 4; ks++) {
            const uint32_t off =
                qrow + (((uint32_t)((2 * ks + (lt >> 1)) ^ ltr)) << 4);
            LDSM4(qhf[ks], sb + off);
            LDSM4(qlf[ks], sb + 16384 + off);
        }
    }
    __syncthreads();

    // ---- K/V tile loader: 1 chunk/thread/array, swizzled ----
    auto load_kv = [&](int c, int s) {
        const uint32_t st = sb + s * ASTG;
        const int row = tid >> 3, cc = tid & 7;       // 32 rows x 8 chunks
        const uint32_t so = (uint32_t)(row * 128 + ((cc ^ (row & 7)) << 4));
        const size_t go = base + (size_t)(c * AKT + row) * Dd + cc * 8;
        CP16(st + 0 * KARR + so, Kh + go);
        CP16(st + 1 * KARR + so, Kl + go);
        CP16(st + 2 * KARR + so, Vh + go);
        CP16(st + 3 * KARR + so, Vl + go);
        CP_COMMIT();
    };

    const uint32_t kb_row = (uint32_t)((ltr + ((lt >> 1) << 3)) * 128);
    const uint32_t vb_row = (uint32_t)((ltr + ((lt & 1) << 3)) * 128);
    const int kc0 = lt & 1;       // K chunk low bit
    const int vc0 = lt >> 1;      // V chunk low bit

    float oacc[8][4];
#pragma unroll
    for (int nb = 0; nb < 8; nb++)
#pragma unroll
        for (int r = 0; r < 4; r++) oacc[nb][r] = 0.0f;
    float sm0 = -1e30f, sm1 = -1e30f, ls0 = 0.0f, ls1 = 0.0f;

    load_kv(0, 0);
    load_kv(1, 1);

    int s = 0;
    for (int c = 0; c < nkt; c++) {
        if (c == nkt - 1) { CP_WAIT(0); } else { CP_WAIT(1); }
        __syncthreads();
        if (c + 2 < nkt) {
            int sn = s + 2; if (sn >= 3) sn -= 3;
            load_kv(c + 2, sn);
        }
        const uint32_t st = sb + s * ASTG;

        // ---- S = Q K^T (3-term bf16): 128 q x 32 keys ----
        float sacc[4][4];
#pragma unroll
        for (int nb = 0; nb < 4; nb++)
#pragma unroll
            for (int r = 0; r < 4; r++) sacc[nb][r] = 0.0f;

#pragma unroll
        for (int ks = 0; ks < 4; ks++) {
#pragma unroll
            for (int ng = 0; ng < 2; ng++) {
                uint32_t kh4[4], kl4[4];
                const uint32_t a = st + kb_row + ng * 2048 +
                    (((uint32_t)((2 * ks + kc0) ^ ltr)) << 4);
                LDSM4(kh4, a);
                LDSM4(kl4, a + KARR);
                MMA_BF16(sacc[2 * ng],     qhf[ks], kh4);
                MMA_BF16(sacc[2 * ng],     qhf[ks], kl4);
                MMA_BF16(sacc[2 * ng],     qlf[ks], kh4);
                MMA_BF16(sacc[2 * ng + 1], qhf[ks], kh4 + 2);
                MMA_BF16(sacc[2 * ng + 1], qhf[ks], kl4 + 2);
                MMA_BF16(sacc[2 * ng + 1], qlf[ks], kh4 + 2);
            }
        }

        // ---- online softmax (Q already scaled; deferred row-sum) ----
        const bool diag = (c >= 4 * qt);
        const int row0 = qt * AQT + w * 16 + (lane >> 2);
        float mx0 = -1e30f, mx1 = -1e30f;
#pragma unroll
        for (int nb = 0; nb < 4; nb++) {
            float s0 = sacc[nb][0], s1 = sacc[nb][1];
            float s2 = sacc[nb][2], s3 = sacc[nb][3];
            if (diag) {
                const int col = c * AKT + nb * 8 + (lane & 3) * 2;
                if (col     > row0)     s0 = -1e30f;
                if (col + 1 > row0)     s1 = -1e30f;
                if (col     > row0 + 8) s2 = -1e30f;
                if (col + 1 > row0 + 8) s3 = -1e30f;
            }
            sacc[nb][0] = s0; sacc[nb][1] = s1; sacc[nb][2] = s2; sacc[nb][3] = s3;
            mx0 = fmaxf(mx0, fmaxf(s0, s1));
            mx1 = fmaxf(mx1, fmaxf(s2, s3));
        }
        mx0 = fmaxf(mx0, __shfl_xor_sync(0xffffffffu, mx0, 1));
        mx0 = fmaxf(mx0, __shfl_xor_sync(0xffffffffu, mx0, 2));
        mx1 = fmaxf(mx1, __shfl_xor_sync(0xffffffffu, mx1, 1));
        mx1 = fmaxf(mx1, __shfl_xor_sync(0xffffffffu, mx1, 2));
        const float mn0 = fmaxf(sm0, mx0), mn1 = fmaxf(sm1, mx1);
        const float al0 = __expf(sm0 - mn0), al1 = __expf(sm1 - mn1);
        float lo0 = 0.0f, lo1 = 0.0f;
#pragma unroll
        for (int nb = 0; nb < 4; nb++) {
            sacc[nb][0] = __expf(sacc[nb][0] - mn0);
            sacc[nb][1] = __expf(sacc[nb][1] - mn0);
            sacc[nb][2] = __expf(sacc[nb][2] - mn1);
            sacc[nb][3] = __expf(sacc[nb][3] - mn1);
            lo0 += sacc[nb][0] + sacc[nb][1];
            lo1 += sacc[nb][2] + sacc[nb][3];
        }
        ls0 = ls0 * al0 + lo0;      // lane-local partial; reduced at the end
        ls1 = ls1 * al1 + lo1;
        sm0 = mn0; sm1 = mn1;
#pragma unroll
        for (int nb = 0; nb < 8; nb++) {
            oacc[nb][0] *= al0; oacc[nb][1] *= al0;
            oacc[nb][2] *= al1; oacc[nb][3] *= al1;
        }

        // ---- O += P V (3-term bf16; V^T frags via ldmatrix.trans) ----
#pragma unroll
        for (int ks = 0; ks < 2; ks++) {
            uint32_t phf4[4], plf4[4];
            phf4[0] = packh2(sacc[2 * ks][0], sacc[2 * ks][1]);
            phf4[1] = packh2(sacc[2 * ks][2], sacc[2 * ks][3]);
            phf4[2] = packh2(sacc[2 * ks + 1][0], sacc[2 * ks + 1][1]);
            phf4[3] = packh2(sacc[2 * ks + 1][2], sacc[2 * ks + 1][3]);
            plf4[0] = packl2(sacc[2 * ks][0], sacc[2 * ks][1]);
            plf4[1] = packl2(sacc[2 * ks][2], sacc[2 * ks][3]);
            plf4[2] = packl2(sacc[2 * ks + 1][0], sacc[2 * ks + 1][1]);
            plf4[3] = packl2(sacc[2 * ks + 1][2], sacc[2 * ks + 1][3]);
#pragma unroll
            for (int dg = 0; dg < 4; dg++) {
                uint32_t vh4[4], vl4[4];
                const uint32_t a = st + 2 * KARR + vb_row + ks * 2048 +
                    (((uint32_t)((2 * dg + vc0) ^ ltr)) << 4);
                LDSMT4(vh4, a);
                LDSMT4(vl4, a + KARR);
                MMA_BF16(oacc[2 * dg],     phf4, vh4);
                MMA_BF16(oacc[2 * dg],     phf4, vl4);
                MMA_BF16(oacc[2 * dg],     plf4, vh4);
                MMA_BF16(oacc[2 * dg + 1], phf4, vh4 + 2);
                MMA_BF16(oacc[2 * dg + 1], phf4, vl4 + 2);
                MMA_BF16(oacc[2 * dg + 1], plf4, vh4 + 2);
            }
        }
        if (++s == 3) s = 0;
    }

    // ---- final row-sum reduce + normalize + write ctx as bf16 hi/lo ----
    ls0 += __shfl_xor_sync(0xffffffffu, ls0, 1);
    ls0 += __shfl_xor_sync(0xffffffffu, ls0, 2);
    ls1 += __shfl_xor_sync(0xffffffffu, ls1, 1);
    ls1 += __shfl_xor_sync(0xffffffffu, ls1, 2);
    const float inv0 = 1.0f / ls0, inv1 = 1.0f / ls1;
    const size_t tr0 = (size_t)(b * Ss + qt * AQT + w * 16 + (lane >> 2));
    const int dcol = h * Hd + (lane & 3) * 2;
#pragma unroll
    for (int nb = 0; nb < 8; nb++) {
        const float o0 = oacc[nb][0] * inv0, o1 = oacc[nb][1] * inv0;
        const float o2 = oacc[nb][2] * inv1, o3 = oacc[nb][3] * inv1;
        const size_t g0 = tr0 * Dd + dcol + nb * 8;
        const size_t g1 = (tr0 + 8) * Dd + dcol + nb * 8;
        *(uint32_t*)(Ch + g0) = packh2(o0, o1);
        *(uint32_t*)(Cl + g0) = packl2(o0, o1);
        *(uint32_t*)(Ch + g1) = packh2(o2, o3);
        *(uint32_t*)(Cl + g1) = packl2(o2, o3);
    }
}

// ---------------------------------------------------------------------------
extern "C" void kernel_launch(void* const* d_in, const int* in_sizes, int n_in,
                              void* d_out, int out_size)
{
    const float* x  = (const float*)d_in[0];
    const float* Wq = (const float*)d_in[1];
    const float* bq = (const float*)d_in[2];
    const float* Wk = (const float*)d_in[3];
    const float* bk = (const float*)d_in[4];
    const float* Wv = (const float*)d_in[5];
    const float* bv = (const float*)d_in[6];
    const float* Wo = (const float*)d_in[7];
    const float* bo = (const float*)d_in[8];
    float* out = (float*)d_out;

    __nv_bfloat16 *xh, *xl, *qh, *ql, *kh, *kl, *vh, *vl, *ch, *cl, *wth, *wtl;
    cudaGetSymbolAddress((void**)&xh, g_xh);
    cudaGetSymbolAddress((void**)&xl, g_xl);
    cudaGetSymbolAddress((void**)&qh, g_qh);
    cudaGetSymbolAddress((void**)&ql, g_ql);
    cudaGetSymbolAddress((void**)&kh, g_kh);
    cudaGetSymbolAddress((void**)&kl, g_kl);
    cudaGetSymbolAddress((void**)&vh, g_vh);
    cudaGetSymbolAddress((void**)&vl, g_vl);
    cudaGetSymbolAddress((void**)&ch, g_ch);
    cudaGetSymbolAddress((void**)&cl, g_cl);
    cudaGetSymbolAddress((void**)&wth, g_wth);
    cudaGetSymbolAddress((void**)&wtl, g_wtl);

    const int WSZ = Dd * Dd;

    transpose_split4_bf16<<<dim3(32, 32, 4), dim3(32, 8)>>>(Wq, Wk, Wv, Wo, wth, wtl);

    split_hilo_bf16<<<(MM * Dd) / 1024, 256>>>(x, xh, xl);

    // Merged QKV projection (Q pre-scaled by 0.125 inside)
    gemm_bf16x3<<<dim3(24, MM / 128), 256, GSMEM>>>(
        xh, xl, wth, wtl, bq, bk, bv,
        qh, ql, kh, kl, vh, vl, nullptr);

    attn_bf16<<<dim3(Ss / AQT, Bb * Hh), 256, ASMEM>>>(qh, ql, kh, kl, vh, vl, ch, cl);

    // Output projection: fp32 result
    gemm_bf16x3<<<dim3(8, MM / 128), 256, GSMEM>>>(
        ch, cl, wth + 3 * (size_t)WSZ, wtl + 3 * (size_t)WSZ, bo, bo, bo,
        nullptr, nullptr, nullptr, nullptr, nullptr, nullptr, out);
}